// round 15
// baseline (speedup 1.0000x reference)
#include <cuda_runtime.h>
#include <cuda_bf16.h>
#include <mma.h>
#include <cstdint>

using namespace nvcuda;

#define TB 256

// ---- problem constants ----
constexpr int Bv = 8, Tv = 1024, Hv = 16, Dv = 64, Cv = 1024, Lv = 256, Ev = 8, Iv = 2048;
constexpr int Nv  = Bv * Tv;   // 8192 tokens
constexpr int BHv = Bv * Hv;   // 128
constexpr int QKVN = Cv + Lv;  // 1280

// ---- scratch (device globals; allocation-free) ----
__device__ float g_kv [Nv * Lv];
__device__ float g_q  [Nv * Cv];
__device__ float g_k  [Nv * Cv];          // [b,h,t,d]
__device__ float g_v  [Nv * Cv];          // [b,h,t,d]
__device__ float g_x1 [Nv * Cv];
__device__ float g_sh [Nv * Cv];
__device__ int   g_sel[Nv];
__device__ float g_p  [Nv];
__device__ int   g_cnt[Ev];
__device__ int   g_off[Ev];
__device__ int   g_cur[Ev];
__device__ int   g_perm[Nv];

// bf16 activation buffers
__device__ __nv_bfloat16 g_hbf  [Nv * Cv];
__device__ __nv_bfloat16 g_h2bf [Nv * Cv];
__device__ __nv_bfloat16 g_atbf [Nv * Cv];
__device__ __nv_bfloat16 g_ubf  [Nv * Iv];
__device__ __nv_bfloat16 g_ucbf [Nv * Iv];

// bf16 weight buffers (converted per launch); row-major [K, N]
__device__ __nv_bfloat16 g_wqkv_bf[Cv * QKVN];         // Wq|Wkv concat on N
__device__ __nv_bfloat16 g_Wo_bf [Cv * Cv];
__device__ __nv_bfloat16 g_s13_bf[Cv * 2 * Iv];        // sw1|sw3 interleaved 128-col blocks
__device__ __nv_bfloat16 g_sw2_bf[Iv * Cv];
__device__ __nv_bfloat16 g_e13_bf[Ev * Cv * 2 * Iv];   // ew1|ew3 interleaved 128-col blocks
__device__ __nv_bfloat16 g_ew2_bf[Ev * Iv * Cv];

__device__ __forceinline__ uint2 f4_to_bf4(float4 v) {
    __nv_bfloat162 lo = __floats2bfloat162_rn(v.x, v.y);
    __nv_bfloat162 hi = __floats2bfloat162_rn(v.z, v.w);
    uint2 r;
    r.x = *reinterpret_cast<unsigned int*>(&lo);
    r.y = *reinterpret_cast<unsigned int*>(&hi);
    return r;
}
__device__ __forceinline__ uint4 f8_to_bf8(float4 v0, float4 v1) {
    uint2 a = f4_to_bf4(v0), b = f4_to_bf4(v1);
    uint4 o; o.x = a.x; o.y = a.y; o.z = b.x; o.w = b.y;
    return o;
}
__device__ __forceinline__ float to_tf32(float x) {
    float r; asm("cvt.rna.tf32.f32 %0, %1;" : "=f"(r) : "f"(x)); return r;
}
__device__ __forceinline__ void cp16(void* sdst, const void* gsrc) {
    uint32_t s = (uint32_t)__cvta_generic_to_shared(sdst);
    asm volatile("cp.async.ca.shared.global [%0], [%1], 16;" :: "r"(s), "l"(gsrc));
}
__device__ __forceinline__ void cp16z(void* sdst, const void* gsrc, bool p) {
    uint32_t s = (uint32_t)__cvta_generic_to_shared(sdst);
    asm volatile("cp.async.ca.shared.global [%0], [%1], 16, %2;" :: "r"(s), "l"(gsrc), "r"(p ? 16 : 0));
}
#define CP_COMMIT() asm volatile("cp.async.commit_group;")
#define CP_WAIT1()  asm volatile("cp.async.wait_group 1;")
#define CP_WAIT0()  asm volatile("cp.async.wait_group 0;")

__device__ __forceinline__ float4 silu4(float4 a, float4 b) {
    float4 r;
    r.x = (a.x / (1.f + expf(-a.x))) * b.x;
    r.y = (a.y / (1.f + expf(-a.y))) * b.y;
    r.z = (a.z / (1.f + expf(-a.z))) * b.z;
    r.w = (a.w / (1.f + expf(-a.w))) * b.w;
    return r;
}

// GEMM dynamic smem: As[3][128][40] + Bs[3][32][264] bf16
constexpr int TG_AS_BYTES = 3 * 128 * 40 * 2;   // 30720
constexpr int TG_SMEM = TG_AS_BYTES + 3 * 32 * 264 * 2;  // 81408

// ============================================================
// fp32 -> bf16 convert (n multiple of 8), 16B stores
// ============================================================
__global__ void f2bf_kernel(const float* __restrict__ in, __nv_bfloat16* __restrict__ out, int n)
{
    int i = (blockIdx.x * TB + threadIdx.x) << 3;
    if (i < n) {
        float4 v0 = *(const float4*)(in + i);
        float4 v1 = *(const float4*)(in + i + 4);
        *(uint4*)(out + i) = f8_to_bf8(v0, v1);
    }
}

// ============================================================
// Strided convert: in [R][1<<shift] fp32 -> out rows of stride ostride
// at column offset ooff. 8 elems/thread, 16B stores.
// ============================================================
__global__ void f2bf_stride(const float* __restrict__ in, __nv_bfloat16* __restrict__ out,
                            int shift, int ostride, int ooff)
{
    int i = (blockIdx.x * TB + threadIdx.x) << 3;
    int r = i >> shift;
    int c = i & ((1 << shift) - 1);
    float4 v0 = *(const float4*)(in + i);
    float4 v1 = *(const float4*)(in + i + 4);
    *(uint4*)(out + (size_t)r * ostride + ooff + c) = f8_to_bf8(v0, v1);
}

// ============================================================
// Paired convert, 128-col interleaved, 8 elems/thread, 16B stores.
// ============================================================
__global__ void f2bf_pair(const float* __restrict__ in1, const float* __restrict__ in2,
                          __nv_bfloat16* __restrict__ out)
{
    size_t zi = (size_t)blockIdx.z * Cv * Iv;
    size_t zo = (size_t)blockIdx.z * Cv * 2 * Iv;
    int i = (blockIdx.x * TB + threadIdx.x) << 3;
    int r = i >> 11;
    int c = i & (Iv - 1);
    int blk = c >> 7, cc = c & 127;
    float4 a0 = *(const float4*)(in1 + zi + i);
    float4 a1 = *(const float4*)(in1 + zi + i + 4);
    float4 b0 = *(const float4*)(in2 + zi + i);
    float4 b1 = *(const float4*)(in2 + zi + i + 4);
    size_t ob = zo + (size_t)r * (2 * Iv) + blk * 256 + cc;
    *(uint4*)(out + ob)       = f8_to_bf8(a0, a1);
    *(uint4*)(out + ob + 128) = f8_to_bf8(b0, b1);
}

// ============================================================
// RMSNorm: one block per token; bf16 output only.
// ============================================================
__global__ void rmsnorm_kernel(const float* __restrict__ x, const float* __restrict__ w,
                               __nv_bfloat16* __restrict__ yb)
{
    int n = blockIdx.x, tid = threadIdx.x;
    const float* xr = x + (size_t)n * Cv;
    __shared__ float red[TB];
    float ss = 0.f;
    for (int c = tid; c < Cv; c += TB) { float v = xr[c]; ss += v * v; }
    red[tid] = ss; __syncthreads();
    for (int s = TB / 2; s > 0; s >>= 1) { if (tid < s) red[tid] += red[tid + s]; __syncthreads(); }
    float rs = rsqrtf(red[0] / (float)Cv + 1e-6f);
    __nv_bfloat16* ybr = yb + (size_t)n * Cv;
    for (int c = tid; c < Cv; c += TB)
        ybr[c] = __float2bfloat16(xr[c] * rs * w[c]);
}

// ============================================================
// RMSNorm + router fused.
// ============================================================
__global__ void rmsnorm_router(const float* __restrict__ x, const float* __restrict__ w,
                               __nv_bfloat16* __restrict__ yb,
                               const float* __restrict__ Wr, const float* __restrict__ rb)
{
    int n = blockIdx.x, tid = threadIdx.x;
    const float* xr = x + (size_t)n * Cv;
    __shared__ float red[TB];
    float ss = 0.f;
    for (int c = tid; c < Cv; c += TB) { float v = xr[c]; ss += v * v; }
    red[tid] = ss; __syncthreads();
    for (int s = TB / 2; s > 0; s >>= 1) { if (tid < s) red[tid] += red[tid + s]; __syncthreads(); }
    float rs = rsqrtf(red[0] / (float)Cv + 1e-6f);
    __nv_bfloat16* ybr = yb + (size_t)n * Cv;
    float part[Ev];
#pragma unroll
    for (int e = 0; e < Ev; e++) part[e] = 0.f;
    for (int c = tid; c < Cv; c += TB) {
        float v = xr[c] * rs * w[c];
        ybr[c] = __float2bfloat16(v);
#pragma unroll
        for (int e = 0; e < Ev; e++) part[e] += v * Wr[c * Ev + e];
    }
    __shared__ float sd[Ev][TB];
#pragma unroll
    for (int e = 0; e < Ev; e++) sd[e][tid] = part[e];
    __syncthreads();
    for (int st = TB / 2; st > 0; st >>= 1) {
        if (tid < st)
#pragma unroll
            for (int e = 0; e < Ev; e++) sd[e][tid] += sd[e][tid + st];
        __syncthreads();
    }
    if (tid == 0) {
        int best = 0; float bp = -1.f;
#pragma unroll
        for (int e = 0; e < Ev; e++) {
            float lg = fminf(fmaxf(sd[e][0] + rb[e], -50.f), 50.f);
            float pr = 1.f / (1.f + expf(-lg));
            if (pr > bp) { bp = pr; best = e; }
        }
        g_sel[n] = best;
        g_p[n]   = fminf(fmaxf(bp, 1e-8f), 1.f - 1e-8f);
    }
}

// ============================================================
// BF16 cp.async 3-stage GEMM, 128x256 block tile, 64x64 warp tile.
// C = alpha*A[M,K]@B[K,N(ldB)] (+Res); C rows stride ldC.
// ============================================================
__global__ void __launch_bounds__(256) tgemm_bf(
    const __nv_bfloat16* __restrict__ A, const __nv_bfloat16* __restrict__ B,
    float* __restrict__ Cmat, const float* __restrict__ Res,
    int K, int ldB, int ldC, float alpha)
{
    extern __shared__ char sm[];
    auto As = (__nv_bfloat16 (*)[128][40])sm;
    auto Bs = (__nv_bfloat16 (*)[32][264])(sm + TG_AS_BYTES);
    const int tid  = threadIdx.x;
    const int warp = tid >> 5;
    const int wm   = warp & 1, wn = warp >> 1;
    const int bm   = blockIdx.y * 128, bn = blockIdx.x * 256;

    wmma::fragment<wmma::accumulator, 16, 16, 16, float> acc[4][4];
#pragma unroll
    for (int mi = 0; mi < 4; mi++)
#pragma unroll
        for (int ni = 0; ni < 4; ni++) wmma::fill_fragment(acc[mi][ni], 0.f);

    const int nch = K >> 5;

    auto issue = [&](int stage, int k0) {
#pragma unroll
        for (int i = 0; i < 2; i++) {
            int ch = (i << 8) + tid;
            int ar = ch >> 2, ac = (ch & 3) << 3;
            cp16(&As[stage][ar][ac], A + (size_t)(bm + ar) * K + k0 + ac);
        }
#pragma unroll
        for (int i = 0; i < 4; i++) {
            int ch = (i << 8) + tid;
            int br = ch >> 5, bc = (ch & 31) << 3;
            cp16(&Bs[stage][br][bc], B + (size_t)(k0 + br) * ldB + bn + bc);
        }
    };

    issue(0, 0);  CP_COMMIT();
    issue(1, 32); CP_COMMIT();

    for (int ch = 0; ch < nch; ch++) {
        CP_WAIT1();
        __syncthreads();
        if (ch + 2 < nch) issue((ch + 2) % 3, (ch + 2) << 5);
        CP_COMMIT();
        int buf = ch % 3;
#pragma unroll
        for (int ks = 0; ks < 2; ks++) {
            int k16 = ks << 4;
            wmma::fragment<wmma::matrix_a, 16, 16, 16, __nv_bfloat16, wmma::row_major> af[4];
            wmma::fragment<wmma::matrix_b, 16, 16, 16, __nv_bfloat16, wmma::row_major> bf[4];
#pragma unroll
            for (int mi = 0; mi < 4; mi++)
                wmma::load_matrix_sync(af[mi], &As[buf][wm * 64 + mi * 16][k16], 40);
#pragma unroll
            for (int ni = 0; ni < 4; ni++)
                wmma::load_matrix_sync(bf[ni], &Bs[buf][k16][wn * 64 + ni * 16], 264);
#pragma unroll
            for (int mi = 0; mi < 4; mi++)
#pragma unroll
                for (int ni = 0; ni < 4; ni++)
                    wmma::mma_sync(acc[mi][ni], af[mi], bf[ni], acc[mi][ni]);
        }
    }

#pragma unroll
    for (int mi = 0; mi < 4; mi++)
#pragma unroll
        for (int ni = 0; ni < 4; ni++) {
            size_t row = (size_t)(bm + wm * 64 + mi * 16);
            size_t col = (size_t)(bn + wn * 64 + ni * 16);
            float* cp = Cmat + row * ldC + col;
            if (Res) {
                wmma::fragment<wmma::accumulator, 16, 16, 16, float> rf;
                wmma::load_matrix_sync(rf, Res + row * ldC + col, ldC, wmma::mem_row_major);
#pragma unroll
                for (int t = 0; t < rf.num_elements; t++)
                    acc[mi][ni].x[t] = acc[mi][ni].x[t] * alpha + rf.x[t];
            } else if (alpha != 1.f) {
#pragma unroll
                for (int t = 0; t < acc[mi][ni].num_elements; t++)
                    acc[mi][ni].x[t] *= alpha;
            }
            wmma::store_matrix_sync(cp, acc[mi][ni], ldC, wmma::mem_row_major);
        }
}

// ============================================================
// BF16 GEMM + fused SiLU epilogue (dense or grouped/gathered).
// ============================================================
template <bool GROUPED>
__global__ void __launch_bounds__(256) tgemm_silu(
    const __nv_bfloat16* __restrict__ A, const __nv_bfloat16* __restrict__ Bbase,
    size_t strideB, int K, __nv_bfloat16* __restrict__ U)
{
    constexpr int N = 2 * Iv;   // 4096
    int cnt = Nv, o = 0, base, bnIdx;
    const __nv_bfloat16* B;
    if (GROUPED) {
        int e = blockIdx.z;
        cnt = g_cnt[e];
        base = blockIdx.x * 128;
        if (base >= cnt) return;
        o = g_off[e];
        bnIdx = blockIdx.y;
        B = Bbase + (size_t)e * strideB;
    } else {
        base = blockIdx.y * 128;
        bnIdx = blockIdx.x;
        B = Bbase;
    }
    const int bn = bnIdx * 256;

    extern __shared__ char sm[];
    auto As = (__nv_bfloat16 (*)[128][40])sm;
    auto Bs = (__nv_bfloat16 (*)[32][264])(sm + TG_AS_BYTES);
    const int tid  = threadIdx.x;
    const int warp = tid >> 5;
    const int wm   = warp & 1, wn = warp >> 1;

    wmma::fragment<wmma::accumulator, 16, 16, 16, float> acc[4][4];
#pragma unroll
    for (int mi = 0; mi < 4; mi++)
#pragma unroll
        for (int ni = 0; ni < 4; ni++) wmma::fill_fragment(acc[mi][ni], 0.f);

    int grow[2]; bool gv[2]; int arr[2]; int arc[2];
#pragma unroll
    for (int i = 0; i < 2; i++) {
        int ch = (i << 8) + tid;
        arr[i] = ch >> 2; arc[i] = (ch & 3) << 3;
        int lr = base + arr[i];
        gv[i] = lr < cnt;
        grow[i] = gv[i] ? (GROUPED ? g_perm[o + lr] : lr) : 0;
    }

    const int nch = K >> 5;

    auto issue = [&](int stg, int k0) {
#pragma unroll
        for (int i = 0; i < 2; i++)
            cp16z(&As[stg][arr[i]][arc[i]], A + (size_t)grow[i] * K + k0 + arc[i], gv[i]);
#pragma unroll
        for (int i = 0; i < 4; i++) {
            int ch = (i << 8) + tid;
            int br = ch >> 5, bc = (ch & 31) << 3;
            cp16(&Bs[stg][br][bc], B + (size_t)(k0 + br) * N + bn + bc);
        }
    };

    issue(0, 0);  CP_COMMIT();
    issue(1, 32); CP_COMMIT();

    for (int ch = 0; ch < nch; ch++) {
        CP_WAIT1();
        __syncthreads();
        if (ch + 2 < nch) issue((ch + 2) % 3, (ch + 2) << 5);
        CP_COMMIT();
        int buf = ch % 3;
#pragma unroll
        for (int ks = 0; ks < 2; ks++) {
            int k16 = ks << 4;
            wmma::fragment<wmma::matrix_a, 16, 16, 16, __nv_bfloat16, wmma::row_major> af[4];
            wmma::fragment<wmma::matrix_b, 16, 16, 16, __nv_bfloat16, wmma::row_major> bf[4];
#pragma unroll
            for (int mi = 0; mi < 4; mi++)
                wmma::load_matrix_sync(af[mi], &As[buf][wm * 64 + mi * 16][k16], 40);
#pragma unroll
            for (int ni = 0; ni < 4; ni++)
                wmma::load_matrix_sync(bf[ni], &Bs[buf][k16][wn * 64 + ni * 16], 264);
#pragma unroll
            for (int mi = 0; mi < 4; mi++)
#pragma unroll
                for (int ni = 0; ni < 4; ni++)
                    wmma::mma_sync(acc[mi][ni], af[mi], bf[ni], acc[mi][ni]);
        }
    }

    __syncthreads();
    float* S = (float*)sm;                  // 32 rows x ldm 264
    const int er = tid >> 3;
    const int ec = (tid & 7) << 4;
#pragma unroll
    for (int mi = 0; mi < 4; mi++) {
#pragma unroll
        for (int ni = 0; ni < 4; ni++)
            wmma::store_matrix_sync(S + (wm * 16) * 264 + wn * 64 + ni * 16,
                                    acc[mi][ni], 264, wmma::mem_row_major);
        __syncthreads();
        int lr = base + (er >> 4) * 64 + mi * 16 + (er & 15);
        if (lr < cnt) {
            size_t row = (size_t)(GROUPED ? (o + lr) : lr);
            __nv_bfloat16* op = U + row * Iv + bnIdx * 128 + ec;
            const float* sp = S + er * 264 + ec;
#pragma unroll
            for (int j = 0; j < 16; j += 4) {
                float4 a = *(const float4*)(sp + j);
                float4 b = *(const float4*)(sp + 128 + j);
                *(uint2*)(op + j) = f4_to_bf4(silu4(a, b));
            }
        }
        __syncthreads();
    }
}

// ============================================================
// Grouped w2 GEMM + fused combine epilogue.
// ============================================================
__global__ void __launch_bounds__(256) gg_w2_combine(
    const __nv_bfloat16* __restrict__ A, const __nv_bfloat16* __restrict__ Bbase,
    size_t strideB, int K,
    const float* __restrict__ x1, const float* __restrict__ sh,
    float* __restrict__ Out)
{
    constexpr int N = Cv;
    int e = blockIdx.z;
    int cnt = g_cnt[e];
    int base = blockIdx.x * 128;
    if (base >= cnt) return;
    int o = g_off[e];
    const __nv_bfloat16* B = Bbase + (size_t)e * strideB;

    extern __shared__ char sm[];
    auto As = (__nv_bfloat16 (*)[128][40])sm;
    auto Bs = (__nv_bfloat16 (*)[32][264])(sm + TG_AS_BYTES);
    const int tid  = threadIdx.x;
    const int warp = tid >> 5;
    const int lane = tid & 31;
    const int wm   = warp & 1, wn = warp >> 1;
    const int bn   = blockIdx.y * 256;

    wmma::fragment<wmma::accumulator, 16, 16, 16, float> acc[4][4];
#pragma unroll
    for (int mi = 0; mi < 4; mi++)
#pragma unroll
        for (int ni = 0; ni < 4; ni++) wmma::fill_fragment(acc[mi][ni], 0.f);

    int grow[2]; bool gv[2]; int arr[2]; int arc[2];
#pragma unroll
    for (int i = 0; i < 2; i++) {
        int ch = (i << 8) + tid;
        arr[i] = ch >> 2; arc[i] = (ch & 3) << 3;
        int lr = base + arr[i];
        gv[i] = lr < cnt;
        grow[i] = gv[i] ? (o + lr) : 0;
    }

    const int nch = K >> 5;

    auto issue = [&](int stg, int k0) {
#pragma unroll
        for (int i = 0; i < 2; i++)
            cp16z(&As[stg][arr[i]][arc[i]], A + (size_t)grow[i] * K + k0 + arc[i], gv[i]);
#pragma unroll
        for (int i = 0; i < 4; i++) {
            int ch = (i << 8) + tid;
            int br = ch >> 5, bc = (ch & 31) << 3;
            cp16(&Bs[stg][br][bc], B + (size_t)(k0 + br) * N + bn + bc);
        }
    };

    issue(0, 0);  CP_COMMIT();
    issue(1, 32); CP_COMMIT();

    for (int ch = 0; ch < nch; ch++) {
        CP_WAIT1();
        __syncthreads();
        if (ch + 2 < nch) issue((ch + 2) % 3, (ch + 2) << 5);
        CP_COMMIT();
        int buf = ch % 3;
#pragma unroll
        for (int ks = 0; ks < 2; ks++) {
            int k16 = ks << 4;
            wmma::fragment<wmma::matrix_a, 16, 16, 16, __nv_bfloat16, wmma::row_major> af[4];
            wmma::fragment<wmma::matrix_b, 16, 16, 16, __nv_bfloat16, wmma::row_major> bf[4];
#pragma unroll
            for (int mi = 0; mi < 4; mi++)
                wmma::load_matrix_sync(af[mi], &As[buf][wm * 64 + mi * 16][k16], 40);
#pragma unroll
            for (int ni = 0; ni < 4; ni++)
                wmma::load_matrix_sync(bf[ni], &Bs[buf][k16][wn * 64 + ni * 16], 264);
#pragma unroll
            for (int mi = 0; mi < 4; mi++)
#pragma unroll
                for (int ni = 0; ni < 4; ni++)
                    wmma::mma_sync(acc[mi][ni], af[mi], bf[ni], acc[mi][ni]);
        }
    }

    __syncthreads();
    float* stg = (float*)sm + warp * 320;
    const int sr = lane >> 1, sc0 = (lane & 1) << 3;
#pragma unroll
    for (int mi = 0; mi < 4; mi++)
#pragma unroll
        for (int ni = 0; ni < 4; ni++) {
            wmma::store_matrix_sync(stg, acc[mi][ni], 20, wmma::mem_row_major);
            __syncwarp();
            int lr = base + wm * 64 + mi * 16 + sr;
            if (lr < cnt) {
                int n = g_perm[o + lr];
                float p = g_p[n];
                float tw = fminf(fmaxf(0.5f + p + 1e-8f, 0.5f), 2.0f);
                float wsh = 0.5f / tw, wex = p / tw;
                int col = bn + wn * 64 + ni * 16 + sc0;
                const float* xr = x1 + (size_t)n * Cv + col;
                const float* sr2 = sh + (size_t)n * Cv + col;
                float* orow = Out + (size_t)n * Cv + col;
                float4 a0 = *(float4*)(stg + sr * 20 + sc0);
                float4 a1 = *(float4*)(stg + sr * 20 + sc0 + 4);
                float4 xv0 = *(const float4*)(xr);
                float4 xv1 = *(const float4*)(xr + 4);
                float4 sv0 = *(const float4*)(sr2);
                float4 sv1 = *(const float4*)(sr2 + 4);
                float4 r0, r1;
                r0.x = xv0.x + wsh * sv0.x + wex * a0.x;
                r0.y = xv0.y + wsh * sv0.y + wex * a0.y;
                r0.z = xv0.z + wsh * sv0.z + wex * a0.z;
                r0.w = xv0.w + wsh * sv0.w + wex * a0.w;
                r1.x = xv1.x + wsh * sv1.x + wex * a1.x;
                r1.y = xv1.y + wsh * sv1.y + wex * a1.y;
                r1.z = xv1.z + wsh * sv1.z + wex * a1.z;
                r1.w = xv1.w + wsh * sv1.w + wex * a1.w;
                *(float4*)(orow)     = r0;
                *(float4*)(orow + 4) = r1;
            }
            __syncwarp();
        }
}

// ============================================================
// K/V up-projection, bf16 wmma. grid (Nv/128, Hv*2). (fp32 inputs)
// ============================================================
__global__ void kvup_wmma(const float* __restrict__ kv,
                          const float* __restrict__ Wk_up, const float* __restrict__ Wv_up,
                          float* __restrict__ kout, float* __restrict__ vout)
{
    int y = blockIdx.y;
    int h = y >> 1, which = y & 1;
    const float* W = (which ? Wv_up : Wk_up) + (size_t)h * Lv * Dv;
    float* outp = which ? vout : kout;
    int bm = blockIdx.x * 128;

    __shared__ __nv_bfloat16 As[2][128][40];
    __shared__ __nv_bfloat16 Bs[2][32][72];
    const int tid  = threadIdx.x;
    const int warp = tid >> 5;
    const int wm   = warp & 3, wn = warp >> 2;

    wmma::fragment<wmma::accumulator, 16, 16, 16, float> acc[2][2];
#pragma unroll
    for (int mi = 0; mi < 2; mi++)
#pragma unroll
        for (int ni = 0; ni < 2; ni++) wmma::fill_fragment(acc[mi][ni], 0.f);

    const int ar0 = tid >> 3, ac = (tid & 7) << 2;
    const int br0 = tid >> 4, bc = (tid & 15) << 2;

    float4 aR[4], bR[2];
    const int nch = Lv >> 5;

#pragma unroll
    for (int i = 0; i < 4; i++)
        aR[i] = *(const float4*)(kv + (size_t)(bm + ar0 + (i << 5)) * Lv + ac);
#pragma unroll
    for (int i = 0; i < 2; i++)
        bR[i] = *(const float4*)(W + (size_t)(br0 + (i << 4)) * Dv + bc);
#pragma unroll
    for (int i = 0; i < 4; i++)
        *(uint2*)&As[0][ar0 + (i << 5)][ac] = f4_to_bf4(aR[i]);
#pragma unroll
    for (int i = 0; i < 2; i++)
        *(uint2*)&Bs[0][br0 + (i << 4)][bc] = f4_to_bf4(bR[i]);
    __syncthreads();

    int cur = 0;
    for (int ch = 0; ch < nch; ch++) {
        bool has = (ch + 1) < nch;
        if (has) {
            int k0 = (ch + 1) << 5;
#pragma unroll
            for (int i = 0; i < 4; i++)
                aR[i] = *(const float4*)(kv + (size_t)(bm + ar0 + (i << 5)) * Lv + k0 + ac);
#pragma unroll
            for (int i = 0; i < 2; i++)
                bR[i] = *(const float4*)(W + (size_t)(k0 + br0 + (i << 4)) * Dv + bc);
        }
#pragma unroll
        for (int ks = 0; ks < 2; ks++) {
            int k16 = ks << 4;
            wmma::fragment<wmma::matrix_a, 16, 16, 16, __nv_bfloat16, wmma::row_major> af[2];
            wmma::fragment<wmma::matrix_b, 16, 16, 16, __nv_bfloat16, wmma::row_major> bf[2];
#pragma unroll
            for (int mi = 0; mi < 2; mi++)
                wmma::load_matrix_sync(af[mi], &As[cur][wm * 32 + mi * 16][k16], 40);
#pragma unroll
            for (int ni = 0; ni < 2; ni++)
                wmma::load_matrix_sync(bf[ni], &Bs[cur][k16][wn * 32 + ni * 16], 72);
#pragma unroll
            for (int mi = 0; mi < 2; mi++)
#pragma unroll
                for (int ni = 0; ni < 2; ni++)
                    wmma::mma_sync(acc[mi][ni], af[mi], bf[ni], acc[mi][ni]);
        }
        if (has) {
            int nxt = cur ^ 1;
#pragma unroll
            for (int i = 0; i < 4; i++)
                *(uint2*)&As[nxt][ar0 + (i << 5)][ac] = f4_to_bf4(aR[i]);
#pragma unroll
            for (int i = 0; i < 2; i++)
                *(uint2*)&Bs[nxt][br0 + (i << 4)][bc] = f4_to_bf4(bR[i]);
        }
        __syncthreads();
        cur ^= 1;
    }

#pragma unroll
    for (int mi = 0; mi < 2; mi++) {
        int n0 = bm + wm * 32 + mi * 16;
        int b = n0 >> 10, t0 = n0 & 1023;
        float* bp = outp + ((size_t)(b * Hv + h) * Tv + t0) * Dv;
#pragma unroll
        for (int ni = 0; ni < 2; ni++)
            wmma::store_matrix_sync(bp + wn * 32 + ni * 16, acc[mi][ni], Dv, wmma::mem_row_major);
    }
}

// ============================================================
// RoPE in place on 64-wide head vectors. posDiv: Hv for q-layout, 1 for k.
// ============================================================
__global__ void rope_kernel(float* __restrict__ xp, int posDiv)
{
    int idx = blockIdx.x * TB + threadIdx.x;
    int outer = idx >> 5;
    int j = idx & 31;
    int pos = (outer / posDiv) & (Tv - 1);
    float invf = powf(100000.0f, -(float)j * (1.0f / 32.0f));
    float f = (float)pos * invf;
    float s, c; sincosf(f, &s, &c);
    float* p = xp + (size_t)outer * Dv;
    float x1 = p[j], x2 = p[j + 32];
    p[j]      = x1 * c - x2 * s;
    p[j + 32] = x1 * s + x2 * c;
}

// ============================================================
// Flash attention, 128-row Q tile, double-buffered K/V (tf32 wmma,
// online softmax). Out bf16 token-major. grid (Tv/128, BHv).
// ============================================================
constexpr int FLASH_SMEM = (3 * 128 * 68 + 4 * 64 * 68 + 3 * 128) * 4;   // ~172KB

__global__ void __launch_bounds__(256) flash_kernel(
    const float* __restrict__ q, const float* __restrict__ k,
    const float* __restrict__ v, __nv_bfloat16* __restrict__ obf)
{
    extern __shared__ float fs[];
    float (*Qs)[68] = (float(*)[68])fs;                               // 128x68
    float (*Os)[68] = (float(*)[68])(fs + 128 * 68);                  // 128x68
    float (*Ss)[68] = (float(*)[68])(fs + 2 * 128 * 68);              // 128x68
    float (*Ks)[64][68] = (float(*)[64][68])(fs + 3 * 128 * 68);      // 2 x 64x68
    float (*Vs)[64][68] = (float(*)[64][68])(fs + 3 * 128 * 68 + 2 * 64 * 68);
    float* mrow = fs + 3 * 128 * 68 + 4 * 64 * 68;
    float* lrow = mrow + 128;
    float* srow = lrow + 128;

    const int qt = blockIdx.x, bh = blockIdx.y;
    const int b = bh >> 4, h = bh & 15;
    const int qs = qt * 128;
    const int tid = threadIdx.x;
    const int warp = tid >> 5;          // 0..7: warp owns rows [warp*16, +16)
    const int row = tid >> 1, qd = tid & 1;

    // load Q tile (128x64): 2048 16B chunks / 256 thr = 8 each
#pragma unroll
    for (int i = 0; i < 8; i++) {
        int ch = (i << 8) + tid;
        int r = ch >> 4, c = (ch & 15) << 2;
        cp16(&Qs[r][c], q + (size_t)(b * Tv + qs + r) * Cv + h * Dv + c);
    }
    CP_COMMIT();
    for (int i = tid; i < 128 * 68; i += 256) (fs + 128 * 68)[i] = 0.f;
    if (tid < 128) { mrow[tid] = -1e30f; lrow[tid] = 0.f; }

    const int ktmax = 2 * qt + 1;
    auto issueKV = [&](int buf, int kt) {
        int ks = kt * 64;
#pragma unroll
        for (int i = 0; i < 4; i++) {
            int ch = (i << 8) + tid;
            int r = ch >> 4, c = (ch & 15) << 2;
            cp16(&Ks[buf][r][c], k + ((size_t)bh * Tv + ks + r) * Dv + c);
            cp16(&Vs[buf][r][c], v + ((size_t)bh * Tv + ks + r) * Dv + c);
        }
    };
    issueKV(0, 0); CP_COMMIT();

    for (int kt = 0; kt <= ktmax; kt++) {
        if (kt < ktmax) { issueKV((kt + 1) & 1, kt + 1); CP_COMMIT(); CP_WAIT1(); }
        else            { CP_WAIT0(); }
        __syncthreads();
        const int buf = kt & 1;
        const int ks = kt * 64;

        // S = Q K^T / 8; warp computes rows [warp*16,+16) x 64 cols
        {
            wmma::fragment<wmma::accumulator, 16, 16, 8, float> a[4];
#pragma unroll
            for (int ni = 0; ni < 4; ni++) wmma::fill_fragment(a[ni], 0.f);
#pragma unroll
            for (int k8 = 0; k8 < 64; k8 += 8) {
                wmma::fragment<wmma::matrix_a, 16, 16, 8, wmma::precision::tf32, wmma::row_major> af;
                wmma::load_matrix_sync(af, &Qs[warp * 16][k8], 68);
#pragma unroll
                for (int ni = 0; ni < 4; ni++) {
                    wmma::fragment<wmma::matrix_b, 16, 16, 8, wmma::precision::tf32, wmma::col_major> bf;
                    wmma::load_matrix_sync(bf, &Ks[buf][ni * 16][k8], 68);
                    wmma::mma_sync(a[ni], af, bf, a[ni]);
                }
            }
#pragma unroll
            for (int ni = 0; ni < 4; ni++) {
#pragma unroll
                for (int t = 0; t < a[ni].num_elements; t++) a[ni].x[t] *= 0.125f;
                wmma::store_matrix_sync(&Ss[warp * 16][ni * 16], a[ni], 68, wmma::mem_row_major);
            }
        }
        __syncthreads();

        // online softmax: 2 threads per row, 32 cols each
        {
            float sv[32];
            float mloc = -1e30f;
#pragma unroll
            for (int i = 0; i < 32; i++) {
                int j = qd + (i << 1);
                float s = Ss[row][j];
                if (ks + j > qs + row) s = -1e30f;
                sv[i] = s;
                mloc = fmaxf(mloc, s);
            }
            mloc = fmaxf(mloc, __shfl_xor_sync(0xffffffffu, mloc, 1));
            float mold = mrow[row];
            float mnew = fmaxf(mold, mloc);
            float psum = 0.f;
#pragma unroll
            for (int i = 0; i < 32; i++) {
                int j = qd + (i << 1);
                float p = (sv[i] > -1e29f) ? expf(sv[i] - mnew) : 0.f;
                Ss[row][j] = to_tf32(p);
                psum += p;
            }
            psum += __shfl_xor_sync(0xffffffffu, psum, 1);
            if (qd == 0) {
                float scl = expf(mold - mnew);
                mrow[row] = mnew;
                lrow[row] = lrow[row] * scl + psum;
                srow[row] = scl;
            }
        }
        __syncthreads();

        // PV -> Ss (reuse; P fragments preloaded before overwrite)
        {
            wmma::fragment<wmma::matrix_a, 16, 16, 8, wmma::precision::tf32, wmma::row_major> af[8];
#pragma unroll
            for (int kk = 0; kk < 8; kk++)
                wmma::load_matrix_sync(af[kk], &Ss[warp * 16][kk * 8], 68);
            __syncthreads();
            wmma::fragment<wmma::accumulator, 16, 16, 8, float> a[4];
#pragma unroll
            for (int ni = 0; ni < 4; ni++) wmma::fill_fragment(a[ni], 0.f);
#pragma unroll
            for (int kk = 0; kk < 8; kk++) {
#pragma unroll
                for (int ni = 0; ni < 4; ni++) {
                    wmma::fragment<wmma::matrix_b, 16, 16, 8, wmma::precision::tf32, wmma::row_major> bf;
                    wmma::load_matrix_sync(bf, &Vs[buf][kk * 8][ni * 16], 68);
                    wmma::mma_sync(a[ni], af[kk], bf, a[ni]);
                }
            }
#pragma unroll
            for (int ni = 0; ni < 4; ni++)
                wmma::store_matrix_sync(&Ss[warp * 16][ni * 16], a[ni], 68, wmma::mem_row_major);
        }
        __syncthreads();

        // O = O*scale + PV
        {
            float scl = srow[row];
#pragma unroll
            for (int i = 0; i < 32; i++) {
                int j = qd + (i << 1);
                Os[row][j] = Os[row][j] * scl + Ss[row][j];
            }
        }
        __syncthreads();
    }

    // epilogue: normalize, write bf16 token-major
    {
        float inv = 1.f / lrow[row];
        __nv_bfloat16* op = obf + (size_t)(b * Tv + qs + row) * Cv + h * Dv;
#pragma unroll
        for (int i = 0; i < 32; i++) {
            int j = qd + (i << 1);
            op[j] = __float2bfloat16(Os[row][j] * inv);
        }
    }
}

__global__ void zero_kernel() {
    int t = threadIdx.x;
    if (t < Ev) { g_cnt[t] = 0; g_cur[t] = 0; }
}
__global__ void hist_kernel() {
    int n = blockIdx.x * TB + threadIdx.x;
    if (n < Nv) atomicAdd(&g_cnt[g_sel[n]], 1);
}
__global__ void offsets_kernel() {
    int s = 0;
    for (int e = 0; e < Ev; e++) { g_off[e] = s; s += g_cnt[e]; }
}
__global__ void scatter_kernel() {
    int n = blockIdx.x * TB + threadIdx.x;
    if (n < Nv) {
        int e = g_sel[n];
        int pos = atomicAdd(&g_cur[e], 1);
        g_perm[g_off[e] + pos] = n;
    }
}

// ============================================================
// Static streams/events (created at program init; no device alloc).
// ============================================================
struct StreamPack {
    cudaStream_t sConv, sAux;
    cudaEvent_t evRoot, evQkv, evWo, evMoe, evAux, evH2, evSh, evNorm, evQ;
    StreamPack() {
        cudaStreamCreateWithFlags(&sConv, cudaStreamNonBlocking);
        cudaStreamCreateWithFlags(&sAux,  cudaStreamNonBlocking);
        cudaEventCreateWithFlags(&evRoot,  cudaEventDisableTiming);
        cudaEventCreateWithFlags(&evQkv,   cudaEventDisableTiming);
        cudaEventCreateWithFlags(&evWo,    cudaEventDisableTiming);
        cudaEventCreateWithFlags(&evMoe,   cudaEventDisableTiming);
        cudaEventCreateWithFlags(&evAux,   cudaEventDisableTiming);
        cudaEventCreateWithFlags(&evH2,    cudaEventDisableTiming);
        cudaEventCreateWithFlags(&evSh,    cudaEventDisableTiming);
        cudaEventCreateWithFlags(&evNorm,  cudaEventDisableTiming);
        cudaEventCreateWithFlags(&evQ,     cudaEventDisableTiming);
    }
};
static StreamPack g_sp;

// ============================================================
// launcher
// ============================================================
extern "C" void kernel_launch(void* const* d_in, const int* in_sizes, int n_in,
                              void* d_out, int out_size)
{
    const float* x    = (const float*)d_in[0];
    const float* ln1  = (const float*)d_in[1];
    const float* ln2  = (const float*)d_in[2];
    const float* Wq   = (const float*)d_in[3];
    const float* Wkv  = (const float*)d_in[4];
    const float* Wk_up= (const float*)d_in[5];
    const float* Wv_up= (const float*)d_in[6];
    const float* Wo   = (const float*)d_in[7];
    const float* Wr   = (const float*)d_in[8];
    const float* rb   = (const float*)d_in[9];
    const float* sw1  = (const float*)d_in[10];
    const float* sw2  = (const float*)d_in[11];
    const float* sw3  = (const float*)d_in[12];
    const float* ew1  = (const float*)d_in[13];
    const float* ew2  = (const float*)d_in[14];
    const float* ew3  = (const float*)d_in[15];
    float* out = (float*)d_out;

    float *pkv, *pq, *pk, *pv, *px1, *psh;
    __nv_bfloat16 *phbf, *ph2bf, *patbf, *pubf, *pucbf;
    __nv_bfloat16 *wqkv, *wo, *s13, *s2, *e13, *e2;
    cudaGetSymbolAddress((void**)&pkv, g_kv);
    cudaGetSymbolAddress((void**)&pq,  g_q);
    cudaGetSymbolAddress((void**)&pk,  g_k);
    cudaGetSymbolAddress((void**)&pv,  g_v);
    cudaGetSymbolAddress((void**)&px1, g_x1);
    cudaGetSymbolAddress((void**)&psh, g_sh);
    cudaGetSymbolAddress((void**)&phbf,  g_hbf);
    cudaGetSymbolAddress((void**)&ph2bf, g_h2bf);
    cudaGetSymbolAddress((void**)&patbf, g_atbf);
    cudaGetSymbolAddress((void**)&pubf,  g_ubf);
    cudaGetSymbolAddress((void**)&pucbf, g_ucbf);
    cudaGetSymbolAddress((void**)&wqkv, g_wqkv_bf);
    cudaGetSymbolAddress((void**)&wo,  g_Wo_bf);
    cudaGetSymbolAddress((void**)&s13, g_s13_bf);
    cudaGetSymbolAddress((void**)&s2,  g_sw2_bf);
    cudaGetSymbolAddress((void**)&e13, g_e13_bf);
    cudaGetSymbolAddress((void**)&e2,  g_ew2_bf);

    cudaFuncSetAttribute(flash_kernel, cudaFuncAttributeMaxDynamicSharedMemorySize, FLASH_SMEM);
    cudaFuncSetAttribute(tgemm_bf, cudaFuncAttributeMaxDynamicSharedMemorySize, TG_SMEM);
    cudaFuncSetAttribute(tgemm_silu<false>, cudaFuncAttributeMaxDynamicSharedMemorySize, TG_SMEM);
    cudaFuncSetAttribute(tgemm_silu<true>,  cudaFuncAttributeMaxDynamicSharedMemorySize, TG_SMEM);
    cudaFuncSetAttribute(gg_w2_combine, cudaFuncAttributeMaxDynamicSharedMemorySize, TG_SMEM);

    cudaStream_t sConv = g_sp.sConv, sAux = g_sp.sAux;

    // ---- fork: weight conversion on side stream ----
    cudaEventRecord(g_sp.evRoot, 0);
    cudaStreamWaitEvent(sConv, g_sp.evRoot, 0);
    f2bf_stride<<<(Cv * Cv) / (TB * 8), TB, 0, sConv>>>(Wq,  wqkv, 10, QKVN, 0);
    f2bf_stride<<<(Cv * Lv) / (TB * 8), TB, 0, sConv>>>(Wkv, wqkv, 8,  QKVN, Cv);
    cudaEventRecord(g_sp.evQkv, sConv);
    f2bf_kernel<<<(Cv * Cv) / (TB * 8), TB, 0, sConv>>>(Wo, wo, Cv * Cv);
    cudaEventRecord(g_sp.evWo, sConv);
    f2bf_pair<<<dim3((Cv * Iv) / (TB * 8), 1, 1),  TB, 0, sConv>>>(sw1, sw3, s13);
    f2bf_kernel<<<(Iv * Cv) / (TB * 8), TB, 0, sConv>>>(sw2, s2, Iv * Cv);
    f2bf_pair<<<dim3((Cv * Iv) / (TB * 8), 1, Ev), TB, 0, sConv>>>(ew1, ew3, e13);
    f2bf_kernel<<<(Ev * Iv * Cv) / (TB * 8), TB, 0, sConv>>>(ew2, e2, Ev * Iv * Cv);
    cudaEventRecord(g_sp.evMoe, sConv);

    // ---- attention ----
    rmsnorm_kernel<<<Nv, TB>>>(x, ln1, phbf);
    cudaEventRecord(g_sp.evNorm, 0);

    // q-slice GEMM + rope_q on sAux (concurrent with kv chain)
    cudaStreamWaitEvent(sAux, g_sp.evNorm, 0);
    cudaStreamWaitEvent(sAux, g_sp.evQkv, 0);
    tgemm_bf<<<dim3(Cv / 256, Nv / 128), TB, TG_SMEM, sAux>>>(phbf, wqkv, pq, nullptr, Cv, QKVN, Cv, 1.f);
    rope_kernel<<<(Nv * Hv * 32) / TB, TB, 0, sAux>>>(pq, Hv);
    cudaEventRecord(g_sp.evQ, sAux);

    // kv-slice GEMM + kvup + rope_k on main
    cudaStreamWaitEvent(0, g_sp.evQkv, 0);
    tgemm_bf<<<dim3(Lv / 256, Nv / 128), TB, TG_SMEM>>>(phbf, wqkv + Cv, pkv, nullptr, Cv, QKVN, Lv, 0.25f);
    kvup_wmma<<<dim3(Nv / 128, Hv * 2), TB>>>(pkv, Wk_up, Wv_up, pk, pv);
    rope_kernel<<<(Nv * Hv * 32) / TB, TB>>>(pk, 1);

    cudaStreamWaitEvent(0, g_sp.evQ, 0);
    flash_kernel<<<dim3(Tv / 128, BHv), TB, FLASH_SMEM>>>(pq, pk, pv, patbf);
    cudaStreamWaitEvent(0, g_sp.evWo, 0);
    tgemm_bf<<<dim3(Cv / 256, Nv / 128), TB, TG_SMEM>>>(patbf, wo, px1, x, Cv, Cv, Cv, 1.f);

    // ---- MoE ----
    rmsnorm_router<<<Nv, TB>>>(px1, ln2, ph2bf, Wr, rb);
    cudaEventRecord(g_sp.evH2, 0);

    // routing bookkeeping on aux stream
    cudaStreamWaitEvent(sAux, g_sp.evH2, 0);
    zero_kernel<<<1, 32, 0, sAux>>>();
    hist_kernel<<<Nv / TB, TB, 0, sAux>>>();
    offsets_kernel<<<1, 1, 0, sAux>>>();
    scatter_kernel<<<Nv / TB, TB, 0, sAux>>>();
    cudaEventRecord(g_sp.evAux, sAux);

    // shared-expert chain on sConv (s13/s2 converts are in-order earlier on sConv)
    cudaStreamWaitEvent(sConv, g_sp.evH2, 0);
    tgemm_silu<false><<<dim3((2 * Iv) / 256, Nv / 128), TB, TG_SMEM, sConv>>>(ph2bf, s13, 0, Cv, pubf);
    tgemm_bf<<<dim3(Cv / 256, Nv / 128), TB, TG_SMEM, sConv>>>(pubf, s2, psh, nullptr, Iv, Cv, Cv, 1.f);
    cudaEventRecord(g_sp.evSh, sConv);

    // routed-expert chain on main stream (concurrent with shared chain)
    cudaStreamWaitEvent(0, g_sp.evMoe, 0);
    cudaStreamWaitEvent(0, g_sp.evAux, 0);
    tgemm_silu<true><<<dim3(Nv / 128, (2 * Iv) / 256, Ev), TB, TG_SMEM>>>(ph2bf, e13, (size_t)Cv * 2 * Iv, Cv, pucbf);
    cudaStreamWaitEvent(0, g_sp.evSh, 0);
    gg_w2_combine<<<dim3(Nv / 128, Cv / 256, Ev), TB, TG_SMEM>>>(pucbf, e2, (size_t)Iv * Cv, Iv, px1, psh, out);
}

// round 16
// speedup vs baseline: 1.0765x; 1.0765x over previous
#include <cuda_runtime.h>
#include <cuda_bf16.h>
#include <mma.h>
#include <cstdint>

using namespace nvcuda;

#define TB 256

// ---- problem constants ----
constexpr int Bv = 8, Tv = 1024, Hv = 16, Dv = 64, Cv = 1024, Lv = 256, Ev = 8, Iv = 2048;
constexpr int Nv  = Bv * Tv;   // 8192 tokens
constexpr int BHv = Bv * Hv;   // 128
constexpr int QKVN = Cv + Lv;  // 1280

// ---- scratch (device globals; allocation-free) ----
__device__ float g_kv [Nv * Lv];
__device__ float g_q  [Nv * Cv];
__device__ float g_k  [Nv * Cv];          // [b,h,t,d]
__device__ float g_v  [Nv * Cv];          // [b,h,t,d]
__device__ float g_x1 [Nv * Cv];
__device__ float g_sh [Nv * Cv];
__device__ int   g_sel[Nv];
__device__ float g_p  [Nv];
__device__ int   g_cnt[Ev];
__device__ int   g_off[Ev];
__device__ int   g_cur[Ev];
__device__ int   g_perm[Nv];

// bf16 activation buffers
__device__ __nv_bfloat16 g_hbf  [Nv * Cv];
__device__ __nv_bfloat16 g_h2bf [Nv * Cv];
__device__ __nv_bfloat16 g_atbf [Nv * Cv];
__device__ __nv_bfloat16 g_ubf  [Nv * Iv];
__device__ __nv_bfloat16 g_ucbf [Nv * Iv];

// bf16 weight buffers (converted per launch); row-major [K, N]
__device__ __nv_bfloat16 g_wqkv_bf[Cv * QKVN];         // Wq|Wkv concat on N
__device__ __nv_bfloat16 g_Wo_bf [Cv * Cv];
__device__ __nv_bfloat16 g_s13_bf[Cv * 2 * Iv];        // sw1|sw3 interleaved 128-col blocks
__device__ __nv_bfloat16 g_sw2_bf[Iv * Cv];
__device__ __nv_bfloat16 g_e13_bf[Ev * Cv * 2 * Iv];   // ew1|ew3 interleaved 128-col blocks
__device__ __nv_bfloat16 g_ew2_bf[Ev * Iv * Cv];

__device__ __forceinline__ uint2 f4_to_bf4(float4 v) {
    __nv_bfloat162 lo = __floats2bfloat162_rn(v.x, v.y);
    __nv_bfloat162 hi = __floats2bfloat162_rn(v.z, v.w);
    uint2 r;
    r.x = *reinterpret_cast<unsigned int*>(&lo);
    r.y = *reinterpret_cast<unsigned int*>(&hi);
    return r;
}
__device__ __forceinline__ uint4 f8_to_bf8(float4 v0, float4 v1) {
    uint2 a = f4_to_bf4(v0), b = f4_to_bf4(v1);
    uint4 o; o.x = a.x; o.y = a.y; o.z = b.x; o.w = b.y;
    return o;
}
__device__ __forceinline__ float to_tf32(float x) {
    float r; asm("cvt.rna.tf32.f32 %0, %1;" : "=f"(r) : "f"(x)); return r;
}
__device__ __forceinline__ void cp16(void* sdst, const void* gsrc) {
    uint32_t s = (uint32_t)__cvta_generic_to_shared(sdst);
    asm volatile("cp.async.ca.shared.global [%0], [%1], 16;" :: "r"(s), "l"(gsrc));
}
__device__ __forceinline__ void cp16z(void* sdst, const void* gsrc, bool p) {
    uint32_t s = (uint32_t)__cvta_generic_to_shared(sdst);
    asm volatile("cp.async.ca.shared.global [%0], [%1], 16, %2;" :: "r"(s), "l"(gsrc), "r"(p ? 16 : 0));
}
#define CP_COMMIT() asm volatile("cp.async.commit_group;")
#define CP_WAIT2()  asm volatile("cp.async.wait_group 2;")
#define CP_WAIT1()  asm volatile("cp.async.wait_group 1;")
#define CP_WAIT0()  asm volatile("cp.async.wait_group 0;")

__device__ __forceinline__ float4 silu4(float4 a, float4 b) {
    float4 r;
    r.x = (a.x / (1.f + expf(-a.x))) * b.x;
    r.y = (a.y / (1.f + expf(-a.y))) * b.y;
    r.z = (a.z / (1.f + expf(-a.z))) * b.z;
    r.w = (a.w / (1.f + expf(-a.w))) * b.w;
    return r;
}

// GEMM dynamic smem: As[3][128][40] + Bs[3][32][264] bf16
constexpr int TG_AS_BYTES = 3 * 128 * 40 * 2;   // 30720
constexpr int TG_SMEM = TG_AS_BYTES + 3 * 32 * 264 * 2;  // 81408

// ============================================================
// fp32 -> bf16 convert (n multiple of 8), 16B stores
// ============================================================
__global__ void f2bf_kernel(const float* __restrict__ in, __nv_bfloat16* __restrict__ out, int n)
{
    int i = (blockIdx.x * TB + threadIdx.x) << 3;
    if (i < n) {
        float4 v0 = *(const float4*)(in + i);
        float4 v1 = *(const float4*)(in + i + 4);
        *(uint4*)(out + i) = f8_to_bf8(v0, v1);
    }
}

// ============================================================
// Strided convert: in [R][1<<shift] fp32 -> out rows of stride ostride
// at column offset ooff. 8 elems/thread, 16B stores.
// ============================================================
__global__ void f2bf_stride(const float* __restrict__ in, __nv_bfloat16* __restrict__ out,
                            int shift, int ostride, int ooff)
{
    int i = (blockIdx.x * TB + threadIdx.x) << 3;
    int r = i >> shift;
    int c = i & ((1 << shift) - 1);
    float4 v0 = *(const float4*)(in + i);
    float4 v1 = *(const float4*)(in + i + 4);
    *(uint4*)(out + (size_t)r * ostride + ooff + c) = f8_to_bf8(v0, v1);
}

// ============================================================
// Paired convert, 128-col interleaved, 8 elems/thread, 16B stores.
// ============================================================
__global__ void f2bf_pair(const float* __restrict__ in1, const float* __restrict__ in2,
                          __nv_bfloat16* __restrict__ out)
{
    size_t zi = (size_t)blockIdx.z * Cv * Iv;
    size_t zo = (size_t)blockIdx.z * Cv * 2 * Iv;
    int i = (blockIdx.x * TB + threadIdx.x) << 3;
    int r = i >> 11;
    int c = i & (Iv - 1);
    int blk = c >> 7, cc = c & 127;
    float4 a0 = *(const float4*)(in1 + zi + i);
    float4 a1 = *(const float4*)(in1 + zi + i + 4);
    float4 b0 = *(const float4*)(in2 + zi + i);
    float4 b1 = *(const float4*)(in2 + zi + i + 4);
    size_t ob = zo + (size_t)r * (2 * Iv) + blk * 256 + cc;
    *(uint4*)(out + ob)       = f8_to_bf8(a0, a1);
    *(uint4*)(out + ob + 128) = f8_to_bf8(b0, b1);
}

// ============================================================
// RMSNorm: one block per token; bf16 output only.
// ============================================================
__global__ void rmsnorm_kernel(const float* __restrict__ x, const float* __restrict__ w,
                               __nv_bfloat16* __restrict__ yb)
{
    int n = blockIdx.x, tid = threadIdx.x;
    const float* xr = x + (size_t)n * Cv;
    __shared__ float red[TB];
    float ss = 0.f;
    for (int c = tid; c < Cv; c += TB) { float v = xr[c]; ss += v * v; }
    red[tid] = ss; __syncthreads();
    for (int s = TB / 2; s > 0; s >>= 1) { if (tid < s) red[tid] += red[tid + s]; __syncthreads(); }
    float rs = rsqrtf(red[0] / (float)Cv + 1e-6f);
    __nv_bfloat16* ybr = yb + (size_t)n * Cv;
    for (int c = tid; c < Cv; c += TB)
        ybr[c] = __float2bfloat16(xr[c] * rs * w[c]);
}

// ============================================================
// RMSNorm + router fused.
// ============================================================
__global__ void rmsnorm_router(const float* __restrict__ x, const float* __restrict__ w,
                               __nv_bfloat16* __restrict__ yb,
                               const float* __restrict__ Wr, const float* __restrict__ rb)
{
    int n = blockIdx.x, tid = threadIdx.x;
    const float* xr = x + (size_t)n * Cv;
    __shared__ float red[TB];
    float ss = 0.f;
    for (int c = tid; c < Cv; c += TB) { float v = xr[c]; ss += v * v; }
    red[tid] = ss; __syncthreads();
    for (int s = TB / 2; s > 0; s >>= 1) { if (tid < s) red[tid] += red[tid + s]; __syncthreads(); }
    float rs = rsqrtf(red[0] / (float)Cv + 1e-6f);
    __nv_bfloat16* ybr = yb + (size_t)n * Cv;
    float part[Ev];
#pragma unroll
    for (int e = 0; e < Ev; e++) part[e] = 0.f;
    for (int c = tid; c < Cv; c += TB) {
        float v = xr[c] * rs * w[c];
        ybr[c] = __float2bfloat16(v);
#pragma unroll
        for (int e = 0; e < Ev; e++) part[e] += v * Wr[c * Ev + e];
    }
    __shared__ float sd[Ev][TB];
#pragma unroll
    for (int e = 0; e < Ev; e++) sd[e][tid] = part[e];
    __syncthreads();
    for (int st = TB / 2; st > 0; st >>= 1) {
        if (tid < st)
#pragma unroll
            for (int e = 0; e < Ev; e++) sd[e][tid] += sd[e][tid + st];
        __syncthreads();
    }
    if (tid == 0) {
        int best = 0; float bp = -1.f;
#pragma unroll
        for (int e = 0; e < Ev; e++) {
            float lg = fminf(fmaxf(sd[e][0] + rb[e], -50.f), 50.f);
            float pr = 1.f / (1.f + expf(-lg));
            if (pr > bp) { bp = pr; best = e; }
        }
        g_sel[n] = best;
        g_p[n]   = fminf(fmaxf(bp, 1e-8f), 1.f - 1e-8f);
    }
}

// ============================================================
// BF16 cp.async 3-stage GEMM, 128x256 block tile, 64x64 warp tile.
// C = alpha*A[M,K]@B[K,N(ldB)] (+Res); C rows stride ldC.
// ============================================================
__global__ void __launch_bounds__(256) tgemm_bf(
    const __nv_bfloat16* __restrict__ A, const __nv_bfloat16* __restrict__ B,
    float* __restrict__ Cmat, const float* __restrict__ Res,
    int K, int ldB, int ldC, float alpha)
{
    extern __shared__ char sm[];
    auto As = (__nv_bfloat16 (*)[128][40])sm;
    auto Bs = (__nv_bfloat16 (*)[32][264])(sm + TG_AS_BYTES);
    const int tid  = threadIdx.x;
    const int warp = tid >> 5;
    const int wm   = warp & 1, wn = warp >> 1;
    const int bm   = blockIdx.y * 128, bn = blockIdx.x * 256;

    wmma::fragment<wmma::accumulator, 16, 16, 16, float> acc[4][4];
#pragma unroll
    for (int mi = 0; mi < 4; mi++)
#pragma unroll
        for (int ni = 0; ni < 4; ni++) wmma::fill_fragment(acc[mi][ni], 0.f);

    const int nch = K >> 5;

    auto issue = [&](int stage, int k0) {
#pragma unroll
        for (int i = 0; i < 2; i++) {
            int ch = (i << 8) + tid;
            int ar = ch >> 2, ac = (ch & 3) << 3;
            cp16(&As[stage][ar][ac], A + (size_t)(bm + ar) * K + k0 + ac);
        }
#pragma unroll
        for (int i = 0; i < 4; i++) {
            int ch = (i << 8) + tid;
            int br = ch >> 5, bc = (ch & 31) << 3;
            cp16(&Bs[stage][br][bc], B + (size_t)(k0 + br) * ldB + bn + bc);
        }
    };

    issue(0, 0);  CP_COMMIT();
    issue(1, 32); CP_COMMIT();

    for (int ch = 0; ch < nch; ch++) {
        CP_WAIT1();
        __syncthreads();
        if (ch + 2 < nch) issue((ch + 2) % 3, (ch + 2) << 5);
        CP_COMMIT();
        int buf = ch % 3;
#pragma unroll
        for (int ks = 0; ks < 2; ks++) {
            int k16 = ks << 4;
            wmma::fragment<wmma::matrix_a, 16, 16, 16, __nv_bfloat16, wmma::row_major> af[4];
            wmma::fragment<wmma::matrix_b, 16, 16, 16, __nv_bfloat16, wmma::row_major> bf[4];
#pragma unroll
            for (int mi = 0; mi < 4; mi++)
                wmma::load_matrix_sync(af[mi], &As[buf][wm * 64 + mi * 16][k16], 40);
#pragma unroll
            for (int ni = 0; ni < 4; ni++)
                wmma::load_matrix_sync(bf[ni], &Bs[buf][k16][wn * 64 + ni * 16], 264);
#pragma unroll
            for (int mi = 0; mi < 4; mi++)
#pragma unroll
                for (int ni = 0; ni < 4; ni++)
                    wmma::mma_sync(acc[mi][ni], af[mi], bf[ni], acc[mi][ni]);
        }
    }

#pragma unroll
    for (int mi = 0; mi < 4; mi++)
#pragma unroll
        for (int ni = 0; ni < 4; ni++) {
            size_t row = (size_t)(bm + wm * 64 + mi * 16);
            size_t col = (size_t)(bn + wn * 64 + ni * 16);
            float* cp = Cmat + row * ldC + col;
            if (Res) {
                wmma::fragment<wmma::accumulator, 16, 16, 16, float> rf;
                wmma::load_matrix_sync(rf, Res + row * ldC + col, ldC, wmma::mem_row_major);
#pragma unroll
                for (int t = 0; t < rf.num_elements; t++)
                    acc[mi][ni].x[t] = acc[mi][ni].x[t] * alpha + rf.x[t];
            } else if (alpha != 1.f) {
#pragma unroll
                for (int t = 0; t < acc[mi][ni].num_elements; t++)
                    acc[mi][ni].x[t] *= alpha;
            }
            wmma::store_matrix_sync(cp, acc[mi][ni], ldC, wmma::mem_row_major);
        }
}

// ============================================================
// BF16 GEMM + fused SiLU epilogue (dense or grouped/gathered).
// ============================================================
template <bool GROUPED>
__global__ void __launch_bounds__(256) tgemm_silu(
    const __nv_bfloat16* __restrict__ A, const __nv_bfloat16* __restrict__ Bbase,
    size_t strideB, int K, __nv_bfloat16* __restrict__ U)
{
    constexpr int N = 2 * Iv;   // 4096
    int cnt = Nv, o = 0, base, bnIdx;
    const __nv_bfloat16* B;
    if (GROUPED) {
        int e = blockIdx.z;
        cnt = g_cnt[e];
        base = blockIdx.x * 128;
        if (base >= cnt) return;
        o = g_off[e];
        bnIdx = blockIdx.y;
        B = Bbase + (size_t)e * strideB;
    } else {
        base = blockIdx.y * 128;
        bnIdx = blockIdx.x;
        B = Bbase;
    }
    const int bn = bnIdx * 256;

    extern __shared__ char sm[];
    auto As = (__nv_bfloat16 (*)[128][40])sm;
    auto Bs = (__nv_bfloat16 (*)[32][264])(sm + TG_AS_BYTES);
    const int tid  = threadIdx.x;
    const int warp = tid >> 5;
    const int wm   = warp & 1, wn = warp >> 1;

    wmma::fragment<wmma::accumulator, 16, 16, 16, float> acc[4][4];
#pragma unroll
    for (int mi = 0; mi < 4; mi++)
#pragma unroll
        for (int ni = 0; ni < 4; ni++) wmma::fill_fragment(acc[mi][ni], 0.f);

    int grow[2]; bool gv[2]; int arr[2]; int arc[2];
#pragma unroll
    for (int i = 0; i < 2; i++) {
        int ch = (i << 8) + tid;
        arr[i] = ch >> 2; arc[i] = (ch & 3) << 3;
        int lr = base + arr[i];
        gv[i] = lr < cnt;
        grow[i] = gv[i] ? (GROUPED ? g_perm[o + lr] : lr) : 0;
    }

    const int nch = K >> 5;

    auto issue = [&](int stg, int k0) {
#pragma unroll
        for (int i = 0; i < 2; i++)
            cp16z(&As[stg][arr[i]][arc[i]], A + (size_t)grow[i] * K + k0 + arc[i], gv[i]);
#pragma unroll
        for (int i = 0; i < 4; i++) {
            int ch = (i << 8) + tid;
            int br = ch >> 5, bc = (ch & 31) << 3;
            cp16(&Bs[stg][br][bc], B + (size_t)(k0 + br) * N + bn + bc);
        }
    };

    issue(0, 0);  CP_COMMIT();
    issue(1, 32); CP_COMMIT();

    for (int ch = 0; ch < nch; ch++) {
        CP_WAIT1();
        __syncthreads();
        if (ch + 2 < nch) issue((ch + 2) % 3, (ch + 2) << 5);
        CP_COMMIT();
        int buf = ch % 3;
#pragma unroll
        for (int ks = 0; ks < 2; ks++) {
            int k16 = ks << 4;
            wmma::fragment<wmma::matrix_a, 16, 16, 16, __nv_bfloat16, wmma::row_major> af[4];
            wmma::fragment<wmma::matrix_b, 16, 16, 16, __nv_bfloat16, wmma::row_major> bf[4];
#pragma unroll
            for (int mi = 0; mi < 4; mi++)
                wmma::load_matrix_sync(af[mi], &As[buf][wm * 64 + mi * 16][k16], 40);
#pragma unroll
            for (int ni = 0; ni < 4; ni++)
                wmma::load_matrix_sync(bf[ni], &Bs[buf][k16][wn * 64 + ni * 16], 264);
#pragma unroll
            for (int mi = 0; mi < 4; mi++)
#pragma unroll
                for (int ni = 0; ni < 4; ni++)
                    wmma::mma_sync(acc[mi][ni], af[mi], bf[ni], acc[mi][ni]);
        }
    }

    __syncthreads();
    float* S = (float*)sm;                  // 32 rows x ldm 264
    const int er = tid >> 3;
    const int ec = (tid & 7) << 4;
#pragma unroll
    for (int mi = 0; mi < 4; mi++) {
#pragma unroll
        for (int ni = 0; ni < 4; ni++)
            wmma::store_matrix_sync(S + (wm * 16) * 264 + wn * 64 + ni * 16,
                                    acc[mi][ni], 264, wmma::mem_row_major);
        __syncthreads();
        int lr = base + (er >> 4) * 64 + mi * 16 + (er & 15);
        if (lr < cnt) {
            size_t row = (size_t)(GROUPED ? (o + lr) : lr);
            __nv_bfloat16* op = U + row * Iv + bnIdx * 128 + ec;
            const float* sp = S + er * 264 + ec;
#pragma unroll
            for (int j = 0; j < 16; j += 4) {
                float4 a = *(const float4*)(sp + j);
                float4 b = *(const float4*)(sp + 128 + j);
                *(uint2*)(op + j) = f4_to_bf4(silu4(a, b));
            }
        }
        __syncthreads();
    }
}

// ============================================================
// Grouped w2 GEMM + fused combine epilogue.
// ============================================================
__global__ void __launch_bounds__(256) gg_w2_combine(
    const __nv_bfloat16* __restrict__ A, const __nv_bfloat16* __restrict__ Bbase,
    size_t strideB, int K,
    const float* __restrict__ x1, const float* __restrict__ sh,
    float* __restrict__ Out)
{
    constexpr int N = Cv;
    int e = blockIdx.z;
    int cnt = g_cnt[e];
    int base = blockIdx.x * 128;
    if (base >= cnt) return;
    int o = g_off[e];
    const __nv_bfloat16* B = Bbase + (size_t)e * strideB;

    extern __shared__ char sm[];
    auto As = (__nv_bfloat16 (*)[128][40])sm;
    auto Bs = (__nv_bfloat16 (*)[32][264])(sm + TG_AS_BYTES);
    const int tid  = threadIdx.x;
    const int warp = tid >> 5;
    const int lane = tid & 31;
    const int wm   = warp & 1, wn = warp >> 1;
    const int bn   = blockIdx.y * 256;

    wmma::fragment<wmma::accumulator, 16, 16, 16, float> acc[4][4];
#pragma unroll
    for (int mi = 0; mi < 4; mi++)
#pragma unroll
        for (int ni = 0; ni < 4; ni++) wmma::fill_fragment(acc[mi][ni], 0.f);

    int grow[2]; bool gv[2]; int arr[2]; int arc[2];
#pragma unroll
    for (int i = 0; i < 2; i++) {
        int ch = (i << 8) + tid;
        arr[i] = ch >> 2; arc[i] = (ch & 3) << 3;
        int lr = base + arr[i];
        gv[i] = lr < cnt;
        grow[i] = gv[i] ? (o + lr) : 0;
    }

    const int nch = K >> 5;

    auto issue = [&](int stg, int k0) {
#pragma unroll
        for (int i = 0; i < 2; i++)
            cp16z(&As[stg][arr[i]][arc[i]], A + (size_t)grow[i] * K + k0 + arc[i], gv[i]);
#pragma unroll
        for (int i = 0; i < 4; i++) {
            int ch = (i << 8) + tid;
            int br = ch >> 5, bc = (ch & 31) << 3;
            cp16(&Bs[stg][br][bc], B + (size_t)(k0 + br) * N + bn + bc);
        }
    };

    issue(0, 0);  CP_COMMIT();
    issue(1, 32); CP_COMMIT();

    for (int ch = 0; ch < nch; ch++) {
        CP_WAIT1();
        __syncthreads();
        if (ch + 2 < nch) issue((ch + 2) % 3, (ch + 2) << 5);
        CP_COMMIT();
        int buf = ch % 3;
#pragma unroll
        for (int ks = 0; ks < 2; ks++) {
            int k16 = ks << 4;
            wmma::fragment<wmma::matrix_a, 16, 16, 16, __nv_bfloat16, wmma::row_major> af[4];
            wmma::fragment<wmma::matrix_b, 16, 16, 16, __nv_bfloat16, wmma::row_major> bf[4];
#pragma unroll
            for (int mi = 0; mi < 4; mi++)
                wmma::load_matrix_sync(af[mi], &As[buf][wm * 64 + mi * 16][k16], 40);
#pragma unroll
            for (int ni = 0; ni < 4; ni++)
                wmma::load_matrix_sync(bf[ni], &Bs[buf][k16][wn * 64 + ni * 16], 264);
#pragma unroll
            for (int mi = 0; mi < 4; mi++)
#pragma unroll
                for (int ni = 0; ni < 4; ni++)
                    wmma::mma_sync(acc[mi][ni], af[mi], bf[ni], acc[mi][ni]);
        }
    }

    __syncthreads();
    float* stg = (float*)sm + warp * 320;
    const int sr = lane >> 1, sc0 = (lane & 1) << 3;
#pragma unroll
    for (int mi = 0; mi < 4; mi++)
#pragma unroll
        for (int ni = 0; ni < 4; ni++) {
            wmma::store_matrix_sync(stg, acc[mi][ni], 20, wmma::mem_row_major);
            __syncwarp();
            int lr = base + wm * 64 + mi * 16 + sr;
            if (lr < cnt) {
                int n = g_perm[o + lr];
                float p = g_p[n];
                float tw = fminf(fmaxf(0.5f + p + 1e-8f, 0.5f), 2.0f);
                float wsh = 0.5f / tw, wex = p / tw;
                int col = bn + wn * 64 + ni * 16 + sc0;
                const float* xr = x1 + (size_t)n * Cv + col;
                const float* sr2 = sh + (size_t)n * Cv + col;
                float* orow = Out + (size_t)n * Cv + col;
                float4 a0 = *(float4*)(stg + sr * 20 + sc0);
                float4 a1 = *(float4*)(stg + sr * 20 + sc0 + 4);
                float4 xv0 = *(const float4*)(xr);
                float4 xv1 = *(const float4*)(xr + 4);
                float4 sv0 = *(const float4*)(sr2);
                float4 sv1 = *(const float4*)(sr2 + 4);
                float4 r0, r1;
                r0.x = xv0.x + wsh * sv0.x + wex * a0.x;
                r0.y = xv0.y + wsh * sv0.y + wex * a0.y;
                r0.z = xv0.z + wsh * sv0.z + wex * a0.z;
                r0.w = xv0.w + wsh * sv0.w + wex * a0.w;
                r1.x = xv1.x + wsh * sv1.x + wex * a1.x;
                r1.y = xv1.y + wsh * sv1.y + wex * a1.y;
                r1.z = xv1.z + wsh * sv1.z + wex * a1.z;
                r1.w = xv1.w + wsh * sv1.w + wex * a1.w;
                *(float4*)(orow)     = r0;
                *(float4*)(orow + 4) = r1;
            }
            __syncwarp();
        }
}

// ============================================================
// K/V up-projection, bf16 wmma. grid (Nv/128, Hv*2). (fp32 inputs)
// ============================================================
__global__ void kvup_wmma(const float* __restrict__ kv,
                          const float* __restrict__ Wk_up, const float* __restrict__ Wv_up,
                          float* __restrict__ kout, float* __restrict__ vout)
{
    int y = blockIdx.y;
    int h = y >> 1, which = y & 1;
    const float* W = (which ? Wv_up : Wk_up) + (size_t)h * Lv * Dv;
    float* outp = which ? vout : kout;
    int bm = blockIdx.x * 128;

    __shared__ __nv_bfloat16 As[2][128][40];
    __shared__ __nv_bfloat16 Bs[2][32][72];
    const int tid  = threadIdx.x;
    const int warp = tid >> 5;
    const int wm   = warp & 3, wn = warp >> 2;

    wmma::fragment<wmma::accumulator, 16, 16, 16, float> acc[2][2];
#pragma unroll
    for (int mi = 0; mi < 2; mi++)
#pragma unroll
        for (int ni = 0; ni < 2; ni++) wmma::fill_fragment(acc[mi][ni], 0.f);

    const int ar0 = tid >> 3, ac = (tid & 7) << 2;
    const int br0 = tid >> 4, bc = (tid & 15) << 2;

    float4 aR[4], bR[2];
    const int nch = Lv >> 5;

#pragma unroll
    for (int i = 0; i < 4; i++)
        aR[i] = *(const float4*)(kv + (size_t)(bm + ar0 + (i << 5)) * Lv + ac);
#pragma unroll
    for (int i = 0; i < 2; i++)
        bR[i] = *(const float4*)(W + (size_t)(br0 + (i << 4)) * Dv + bc);
#pragma unroll
    for (int i = 0; i < 4; i++)
        *(uint2*)&As[0][ar0 + (i << 5)][ac] = f4_to_bf4(aR[i]);
#pragma unroll
    for (int i = 0; i < 2; i++)
        *(uint2*)&Bs[0][br0 + (i << 4)][bc] = f4_to_bf4(bR[i]);
    __syncthreads();

    int cur = 0;
    for (int ch = 0; ch < nch; ch++) {
        bool has = (ch + 1) < nch;
        if (has) {
            int k0 = (ch + 1) << 5;
#pragma unroll
            for (int i = 0; i < 4; i++)
                aR[i] = *(const float4*)(kv + (size_t)(bm + ar0 + (i << 5)) * Lv + k0 + ac);
#pragma unroll
            for (int i = 0; i < 2; i++)
                bR[i] = *(const float4*)(W + (size_t)(k0 + br0 + (i << 4)) * Dv + bc);
        }
#pragma unroll
        for (int ks = 0; ks < 2; ks++) {
            int k16 = ks << 4;
            wmma::fragment<wmma::matrix_a, 16, 16, 16, __nv_bfloat16, wmma::row_major> af[2];
            wmma::fragment<wmma::matrix_b, 16, 16, 16, __nv_bfloat16, wmma::row_major> bf[2];
#pragma unroll
            for (int mi = 0; mi < 2; mi++)
                wmma::load_matrix_sync(af[mi], &As[cur][wm * 32 + mi * 16][k16], 40);
#pragma unroll
            for (int ni = 0; ni < 2; ni++)
                wmma::load_matrix_sync(bf[ni], &Bs[cur][k16][wn * 32 + ni * 16], 72);
#pragma unroll
            for (int mi = 0; mi < 2; mi++)
#pragma unroll
                for (int ni = 0; ni < 2; ni++)
                    wmma::mma_sync(acc[mi][ni], af[mi], bf[ni], acc[mi][ni]);
        }
        if (has) {
            int nxt = cur ^ 1;
#pragma unroll
            for (int i = 0; i < 4; i++)
                *(uint2*)&As[nxt][ar0 + (i << 5)][ac] = f4_to_bf4(aR[i]);
#pragma unroll
            for (int i = 0; i < 2; i++)
                *(uint2*)&Bs[nxt][br0 + (i << 4)][bc] = f4_to_bf4(bR[i]);
        }
        __syncthreads();
        cur ^= 1;
    }

#pragma unroll
    for (int mi = 0; mi < 2; mi++) {
        int n0 = bm + wm * 32 + mi * 16;
        int b = n0 >> 10, t0 = n0 & 1023;
        float* bp = outp + ((size_t)(b * Hv + h) * Tv + t0) * Dv;
#pragma unroll
        for (int ni = 0; ni < 2; ni++)
            wmma::store_matrix_sync(bp + wn * 32 + ni * 16, acc[mi][ni], Dv, wmma::mem_row_major);
    }
}

// ============================================================
// RoPE in place on 64-wide head vectors. posDiv: Hv for q-layout, 1 for k.
// ============================================================
__global__ void rope_kernel(float* __restrict__ xp, int posDiv)
{
    int idx = blockIdx.x * TB + threadIdx.x;
    int outer = idx >> 5;
    int j = idx & 31;
    int pos = (outer / posDiv) & (Tv - 1);
    float invf = powf(100000.0f, -(float)j * (1.0f / 32.0f));
    float f = (float)pos * invf;
    float s, c; sincosf(f, &s, &c);
    float* p = xp + (size_t)outer * Dv;
    float x1 = p[j], x2 = p[j + 32];
    p[j]      = x1 * c - x2 * s;
    p[j + 32] = x1 * s + x2 * c;
}

// ============================================================
// Flash attention, 64-row Q tile, K double-buffered + V late-wait
// (tf32 wmma, online softmax). Out bf16 token-major. grid (Tv/64, BHv).
// ============================================================
constexpr int FLASH_SMEM = (6 * 64 * 68 + 3 * 64) * 4;   // ~102.8KB -> 2 blocks/SM

__global__ void __launch_bounds__(256) flash_kernel(
    const float* __restrict__ q, const float* __restrict__ k,
    const float* __restrict__ v, __nv_bfloat16* __restrict__ obf)
{
    extern __shared__ float fs[];
    float (*Qs)[68] = (float(*)[68])fs;
    float (*Os)[68] = (float(*)[68])(fs + 64 * 68);
    float (*Ss)[68] = (float(*)[68])(fs + 2 * 64 * 68);
    float (*Ks)[64][68] = (float(*)[64][68])(fs + 3 * 64 * 68);   // 2 buffers
    float (*Vs)[68] = (float(*)[68])(fs + 5 * 64 * 68);
    float* mrow = fs + 6 * 64 * 68;
    float* lrow = mrow + 64;
    float* srow = lrow + 64;

    const int qt = blockIdx.x, bh = blockIdx.y;
    const int b = bh >> 4, h = bh & 15;
    const int qs = qt * 64;
    const int tid = threadIdx.x;
    const int warp = tid >> 5;
    const int wm = warp & 3, wn = warp >> 2;
    const int row = tid >> 2, qd = tid & 3;

    // load Q tile (group Q)
#pragma unroll
    for (int i = 0; i < 4; i++) {
        int ch = (i << 8) + tid;
        int r = ch >> 4, c = (ch & 15) << 2;
        cp16(&Qs[r][c], q + (size_t)(b * Tv + qs + r) * Cv + h * Dv + c);
    }
    CP_COMMIT();
    for (int i = tid; i < 64 * 68; i += 256) (fs + 64 * 68)[i] = 0.f;
    if (tid < 64) { mrow[tid] = -1e30f; lrow[tid] = 0.f; }

    auto issueK = [&](int buf, int kt) {
        int ks = kt * 64;
#pragma unroll
        for (int i = 0; i < 4; i++) {
            int ch = (i << 8) + tid;
            int r = ch >> 4, c = (ch & 15) << 2;
            cp16(&Ks[buf][r][c], k + ((size_t)bh * Tv + ks + r) * Dv + c);
        }
    };
    issueK(0, 0); CP_COMMIT();   // pending: Q, K0

    for (int kt = 0; kt <= qt; kt++) {
        int ks = kt * 64;
        // issue V[kt]
#pragma unroll
        for (int i = 0; i < 4; i++) {
            int ch = (i << 8) + tid;
            int r = ch >> 4, c = (ch & 15) << 2;
            cp16(&Vs[r][c], v + ((size_t)bh * Tv + ks + r) * Dv + c);
        }
        CP_COMMIT();
        bool has = kt < qt;
        if (has) { issueK((kt + 1) & 1, kt + 1); CP_COMMIT(); CP_WAIT2(); }
        else     { CP_WAIT1(); }
        __syncthreads();
        const int buf = kt & 1;

        // S = Q K^T / 8 -> Ss
        {
            wmma::fragment<wmma::accumulator, 16, 16, 8, float> a0, a1;
            wmma::fill_fragment(a0, 0.f); wmma::fill_fragment(a1, 0.f);
#pragma unroll
            for (int k8 = 0; k8 < 64; k8 += 8) {
                wmma::fragment<wmma::matrix_a, 16, 16, 8, wmma::precision::tf32, wmma::row_major> af;
                wmma::fragment<wmma::matrix_b, 16, 16, 8, wmma::precision::tf32, wmma::col_major> bf0, bf1;
                wmma::load_matrix_sync(af, &Qs[wm * 16][k8], 68);
                wmma::load_matrix_sync(bf0, &Ks[buf][wn * 32][k8], 68);
                wmma::load_matrix_sync(bf1, &Ks[buf][wn * 32 + 16][k8], 68);
                wmma::mma_sync(a0, af, bf0, a0);
                wmma::mma_sync(a1, af, bf1, a1);
            }
#pragma unroll
            for (int t = 0; t < a0.num_elements; t++) { a0.x[t] *= 0.125f; a1.x[t] *= 0.125f; }
            wmma::store_matrix_sync(&Ss[wm * 16][wn * 32], a0, 68, wmma::mem_row_major);
            wmma::store_matrix_sync(&Ss[wm * 16][wn * 32 + 16], a1, 68, wmma::mem_row_major);
        }
        __syncthreads();

        // online softmax row update
        {
            const bool diag = (kt == qt);
            float sv[16];
            float mloc = -1e30f;
#pragma unroll
            for (int i = 0; i < 16; i++) {
                int j = qd + (i << 2);
                float s = Ss[row][j];
                if (diag && j > row) s = -1e30f;
                sv[i] = s;
                mloc = fmaxf(mloc, s);
            }
            mloc = fmaxf(mloc, __shfl_xor_sync(0xffffffffu, mloc, 1));
            mloc = fmaxf(mloc, __shfl_xor_sync(0xffffffffu, mloc, 2));
            float mold = mrow[row];
            float mnew = fmaxf(mold, mloc);
            float psum = 0.f;
#pragma unroll
            for (int i = 0; i < 16; i++) {
                int j = qd + (i << 2);
                float p = (sv[i] > -1e29f) ? expf(sv[i] - mnew) : 0.f;
                Ss[row][j] = to_tf32(p);
                psum += p;
            }
            psum += __shfl_xor_sync(0xffffffffu, psum, 1);
            psum += __shfl_xor_sync(0xffffffffu, psum, 2);
            if (qd == 0) {
                float scl = expf(mold - mnew);
                mrow[row] = mnew;
                lrow[row] = lrow[row] * scl + psum;
                srow[row] = scl;
            }
        }
        // wait for V[kt] (hidden behind QK + softmax)
        if (has) CP_WAIT1(); else CP_WAIT0();
        __syncthreads();

        // PV -> Ss (reuse; P fragments preloaded before overwrite)
        {
            wmma::fragment<wmma::matrix_a, 16, 16, 8, wmma::precision::tf32, wmma::row_major> af[8];
#pragma unroll
            for (int kk = 0; kk < 8; kk++)
                wmma::load_matrix_sync(af[kk], &Ss[wm * 16][kk * 8], 68);
            __syncthreads();
            wmma::fragment<wmma::accumulator, 16, 16, 8, float> a0, a1;
            wmma::fill_fragment(a0, 0.f); wmma::fill_fragment(a1, 0.f);
#pragma unroll
            for (int kk = 0; kk < 8; kk++) {
                wmma::fragment<wmma::matrix_b, 16, 16, 8, wmma::precision::tf32, wmma::row_major> bf0, bf1;
                wmma::load_matrix_sync(bf0, &Vs[kk * 8][wn * 32], 68);
                wmma::load_matrix_sync(bf1, &Vs[kk * 8][wn * 32 + 16], 68);
                wmma::mma_sync(a0, af[kk], bf0, a0);
                wmma::mma_sync(a1, af[kk], bf1, a1);
            }
            wmma::store_matrix_sync(&Ss[wm * 16][wn * 32], a0, 68, wmma::mem_row_major);
            wmma::store_matrix_sync(&Ss[wm * 16][wn * 32 + 16], a1, 68, wmma::mem_row_major);
        }
        __syncthreads();

        // O = O*scale + PV
        {
            float scl = srow[row];
#pragma unroll
            for (int i = 0; i < 16; i++) {
                int j = qd + (i << 2);
                Os[row][j] = Os[row][j] * scl + Ss[row][j];
            }
        }
        __syncthreads();
    }

    // epilogue: normalize, write bf16 token-major
    {
        float inv = 1.f / lrow[row];
        __nv_bfloat16* op = obf + (size_t)(b * Tv + qs + row) * Cv + h * Dv;
#pragma unroll
        for (int i = 0; i < 16; i++) {
            int j = qd + (i << 2);
            op[j] = __float2bfloat16(Os[row][j] * inv);
        }
    }
}

__global__ void zero_kernel() {
    int t = threadIdx.x;
    if (t < Ev) { g_cnt[t] = 0; g_cur[t] = 0; }
}
__global__ void hist_kernel() {
    int n = blockIdx.x * TB + threadIdx.x;
    if (n < Nv) atomicAdd(&g_cnt[g_sel[n]], 1);
}
__global__ void offsets_kernel() {
    int s = 0;
    for (int e = 0; e < Ev; e++) { g_off[e] = s; s += g_cnt[e]; }
}
__global__ void scatter_kernel() {
    int n = blockIdx.x * TB + threadIdx.x;
    if (n < Nv) {
        int e = g_sel[n];
        int pos = atomicAdd(&g_cur[e], 1);
        g_perm[g_off[e] + pos] = n;
    }
}

// ============================================================
// Static streams/events (created at program init; no device alloc).
// ============================================================
struct StreamPack {
    cudaStream_t sConv, sAux;
    cudaEvent_t evRoot, evQkv, evWo, evMoe, evAux, evH2, evSh, evNorm, evQ;
    StreamPack() {
        cudaStreamCreateWithFlags(&sConv, cudaStreamNonBlocking);
        cudaStreamCreateWithFlags(&sAux,  cudaStreamNonBlocking);
        cudaEventCreateWithFlags(&evRoot,  cudaEventDisableTiming);
        cudaEventCreateWithFlags(&evQkv,   cudaEventDisableTiming);
        cudaEventCreateWithFlags(&evWo,    cudaEventDisableTiming);
        cudaEventCreateWithFlags(&evMoe,   cudaEventDisableTiming);
        cudaEventCreateWithFlags(&evAux,   cudaEventDisableTiming);
        cudaEventCreateWithFlags(&evH2,    cudaEventDisableTiming);
        cudaEventCreateWithFlags(&evSh,    cudaEventDisableTiming);
        cudaEventCreateWithFlags(&evNorm,  cudaEventDisableTiming);
        cudaEventCreateWithFlags(&evQ,     cudaEventDisableTiming);
    }
};
static StreamPack g_sp;

// ============================================================
// launcher
// ============================================================
extern "C" void kernel_launch(void* const* d_in, const int* in_sizes, int n_in,
                              void* d_out, int out_size)
{
    const float* x    = (const float*)d_in[0];
    const float* ln1  = (const float*)d_in[1];
    const float* ln2  = (const float*)d_in[2];
    const float* Wq   = (const float*)d_in[3];
    const float* Wkv  = (const float*)d_in[4];
    const float* Wk_up= (const float*)d_in[5];
    const float* Wv_up= (const float*)d_in[6];
    const float* Wo   = (const float*)d_in[7];
    const float* Wr   = (const float*)d_in[8];
    const float* rb   = (const float*)d_in[9];
    const float* sw1  = (const float*)d_in[10];
    const float* sw2  = (const float*)d_in[11];
    const float* sw3  = (const float*)d_in[12];
    const float* ew1  = (const float*)d_in[13];
    const float* ew2  = (const float*)d_in[14];
    const float* ew3  = (const float*)d_in[15];
    float* out = (float*)d_out;

    float *pkv, *pq, *pk, *pv, *px1, *psh;
    __nv_bfloat16 *phbf, *ph2bf, *patbf, *pubf, *pucbf;
    __nv_bfloat16 *wqkv, *wo, *s13, *s2, *e13, *e2;
    cudaGetSymbolAddress((void**)&pkv, g_kv);
    cudaGetSymbolAddress((void**)&pq,  g_q);
    cudaGetSymbolAddress((void**)&pk,  g_k);
    cudaGetSymbolAddress((void**)&pv,  g_v);
    cudaGetSymbolAddress((void**)&px1, g_x1);
    cudaGetSymbolAddress((void**)&psh, g_sh);
    cudaGetSymbolAddress((void**)&phbf,  g_hbf);
    cudaGetSymbolAddress((void**)&ph2bf, g_h2bf);
    cudaGetSymbolAddress((void**)&patbf, g_atbf);
    cudaGetSymbolAddress((void**)&pubf,  g_ubf);
    cudaGetSymbolAddress((void**)&pucbf, g_ucbf);
    cudaGetSymbolAddress((void**)&wqkv, g_wqkv_bf);
    cudaGetSymbolAddress((void**)&wo,  g_Wo_bf);
    cudaGetSymbolAddress((void**)&s13, g_s13_bf);
    cudaGetSymbolAddress((void**)&s2,  g_sw2_bf);
    cudaGetSymbolAddress((void**)&e13, g_e13_bf);
    cudaGetSymbolAddress((void**)&e2,  g_ew2_bf);

    cudaFuncSetAttribute(flash_kernel, cudaFuncAttributeMaxDynamicSharedMemorySize, FLASH_SMEM);
    cudaFuncSetAttribute(tgemm_bf, cudaFuncAttributeMaxDynamicSharedMemorySize, TG_SMEM);
    cudaFuncSetAttribute(tgemm_silu<false>, cudaFuncAttributeMaxDynamicSharedMemorySize, TG_SMEM);
    cudaFuncSetAttribute(tgemm_silu<true>,  cudaFuncAttributeMaxDynamicSharedMemorySize, TG_SMEM);
    cudaFuncSetAttribute(gg_w2_combine, cudaFuncAttributeMaxDynamicSharedMemorySize, TG_SMEM);

    cudaStream_t sConv = g_sp.sConv, sAux = g_sp.sAux;

    // ---- fork: weight conversion on side stream ----
    cudaEventRecord(g_sp.evRoot, 0);
    cudaStreamWaitEvent(sConv, g_sp.evRoot, 0);
    f2bf_stride<<<(Cv * Cv) / (TB * 8), TB, 0, sConv>>>(Wq,  wqkv, 10, QKVN, 0);
    f2bf_stride<<<(Cv * Lv) / (TB * 8), TB, 0, sConv>>>(Wkv, wqkv, 8,  QKVN, Cv);
    cudaEventRecord(g_sp.evQkv, sConv);
    f2bf_kernel<<<(Cv * Cv) / (TB * 8), TB, 0, sConv>>>(Wo, wo, Cv * Cv);
    cudaEventRecord(g_sp.evWo, sConv);
    f2bf_pair<<<dim3((Cv * Iv) / (TB * 8), 1, 1),  TB, 0, sConv>>>(sw1, sw3, s13);
    f2bf_kernel<<<(Iv * Cv) / (TB * 8), TB, 0, sConv>>>(sw2, s2, Iv * Cv);
    f2bf_pair<<<dim3((Cv * Iv) / (TB * 8), 1, Ev), TB, 0, sConv>>>(ew1, ew3, e13);
    f2bf_kernel<<<(Ev * Iv * Cv) / (TB * 8), TB, 0, sConv>>>(ew2, e2, Ev * Iv * Cv);
    cudaEventRecord(g_sp.evMoe, sConv);

    // ---- attention ----
    rmsnorm_kernel<<<Nv, TB>>>(x, ln1, phbf);
    cudaEventRecord(g_sp.evNorm, 0);

    // q-slice GEMM + rope_q on sAux (concurrent with kv chain)
    cudaStreamWaitEvent(sAux, g_sp.evNorm, 0);
    cudaStreamWaitEvent(sAux, g_sp.evQkv, 0);
    tgemm_bf<<<dim3(Cv / 256, Nv / 128), TB, TG_SMEM, sAux>>>(phbf, wqkv, pq, nullptr, Cv, QKVN, Cv, 1.f);
    rope_kernel<<<(Nv * Hv * 32) / TB, TB, 0, sAux>>>(pq, Hv);
    cudaEventRecord(g_sp.evQ, sAux);

    // kv-slice GEMM + kvup + rope_k on main
    cudaStreamWaitEvent(0, g_sp.evQkv, 0);
    tgemm_bf<<<dim3(Lv / 256, Nv / 128), TB, TG_SMEM>>>(phbf, wqkv + Cv, pkv, nullptr, Cv, QKVN, Lv, 0.25f);
    kvup_wmma<<<dim3(Nv / 128, Hv * 2), TB>>>(pkv, Wk_up, Wv_up, pk, pv);
    rope_kernel<<<(Nv * Hv * 32) / TB, TB>>>(pk, 1);

    cudaStreamWaitEvent(0, g_sp.evQ, 0);
    flash_kernel<<<dim3(Tv / 64, BHv), TB, FLASH_SMEM>>>(pq, pk, pv, patbf);
    cudaStreamWaitEvent(0, g_sp.evWo, 0);
    tgemm_bf<<<dim3(Cv / 256, Nv / 128), TB, TG_SMEM>>>(patbf, wo, px1, x, Cv, Cv, Cv, 1.f);

    // ---- MoE ----
    rmsnorm_router<<<Nv, TB>>>(px1, ln2, ph2bf, Wr, rb);
    cudaEventRecord(g_sp.evH2, 0);

    // routing bookkeeping on aux stream
    cudaStreamWaitEvent(sAux, g_sp.evH2, 0);
    zero_kernel<<<1, 32, 0, sAux>>>();
    hist_kernel<<<Nv / TB, TB, 0, sAux>>>();
    offsets_kernel<<<1, 1, 0, sAux>>>();
    scatter_kernel<<<Nv / TB, TB, 0, sAux>>>();
    cudaEventRecord(g_sp.evAux, sAux);

    // shared-expert chain on sConv (s13/s2 converts are in-order earlier on sConv)
    cudaStreamWaitEvent(sConv, g_sp.evH2, 0);
    tgemm_silu<false><<<dim3((2 * Iv) / 256, Nv / 128), TB, TG_SMEM, sConv>>>(ph2bf, s13, 0, Cv, pubf);
    tgemm_bf<<<dim3(Cv / 256, Nv / 128), TB, TG_SMEM, sConv>>>(pubf, s2, psh, nullptr, Iv, Cv, Cv, 1.f);
    cudaEventRecord(g_sp.evSh, sConv);

    // routed-expert chain on main stream (concurrent with shared chain)
    cudaStreamWaitEvent(0, g_sp.evMoe, 0);
    cudaStreamWaitEvent(0, g_sp.evAux, 0);
    tgemm_silu<true><<<dim3(Nv / 128, (2 * Iv) / 256, Ev), TB, TG_SMEM>>>(ph2bf, e13, (size_t)Cv * 2 * Iv, Cv, pucbf);
    cudaStreamWaitEvent(0, g_sp.evSh, 0);
    gg_w2_combine<<<dim3(Nv / 128, Cv / 256, Ev), TB, TG_SMEM>>>(pucbf, e2, (size_t)Iv * Cv, Iv, px1, psh, out);
}

// round 17
// speedup vs baseline: 1.1379x; 1.0571x over previous
#include <cuda_runtime.h>
#include <cuda_bf16.h>
#include <mma.h>
#include <cstdint>

using namespace nvcuda;

#define TB 256

// ---- problem constants ----
constexpr int Bv = 8, Tv = 1024, Hv = 16, Dv = 64, Cv = 1024, Lv = 256, Ev = 8, Iv = 2048;
constexpr int Nv  = Bv * Tv;   // 8192 tokens
constexpr int BHv = Bv * Hv;   // 128
constexpr int QKVN = Cv + Lv;  // 1280

// ---- scratch (device globals; allocation-free) ----
__device__ float g_kv [Nv * Lv];
__device__ float g_q  [Nv * Cv];
__device__ float g_k  [Nv * Cv];          // [b,h,t,d]
__device__ float g_v  [Nv * Cv];          // [b,h,t,d]
__device__ float g_x1 [Nv * Cv];
__device__ float g_sh [Nv * Cv];
__device__ int   g_sel[Nv];
__device__ float g_p  [Nv];
__device__ int   g_cnt[Ev];
__device__ int   g_off[Ev];
__device__ int   g_cur[Ev];
__device__ int   g_perm[Nv];

// bf16 activation buffers
__device__ __nv_bfloat16 g_hbf  [Nv * Cv];
__device__ __nv_bfloat16 g_h2bf [Nv * Cv];
__device__ __nv_bfloat16 g_atbf [Nv * Cv];
__device__ __nv_bfloat16 g_ubf  [Nv * Iv];
__device__ __nv_bfloat16 g_ucbf [Nv * Iv];

// bf16 weight buffers (converted per launch); row-major [K, N]
__device__ __nv_bfloat16 g_wqkv_bf[Cv * QKVN];         // Wq|Wkv concat on N
__device__ __nv_bfloat16 g_Wo_bf [Cv * Cv];
__device__ __nv_bfloat16 g_s13_bf[Cv * 2 * Iv];        // sw1|sw3 interleaved 128-col blocks
__device__ __nv_bfloat16 g_sw2_bf[Iv * Cv];
__device__ __nv_bfloat16 g_e13_bf[Ev * Cv * 2 * Iv];   // ew1|ew3 interleaved 128-col blocks
__device__ __nv_bfloat16 g_ew2_bf[Ev * Iv * Cv];

__device__ __forceinline__ uint2 f4_to_bf4(float4 v) {
    __nv_bfloat162 lo = __floats2bfloat162_rn(v.x, v.y);
    __nv_bfloat162 hi = __floats2bfloat162_rn(v.z, v.w);
    uint2 r;
    r.x = *reinterpret_cast<unsigned int*>(&lo);
    r.y = *reinterpret_cast<unsigned int*>(&hi);
    return r;
}
__device__ __forceinline__ uint4 f8_to_bf8(float4 v0, float4 v1) {
    uint2 a = f4_to_bf4(v0), b = f4_to_bf4(v1);
    uint4 o; o.x = a.x; o.y = a.y; o.z = b.x; o.w = b.y;
    return o;
}
__device__ __forceinline__ float to_tf32(float x) {
    float r; asm("cvt.rna.tf32.f32 %0, %1;" : "=f"(r) : "f"(x)); return r;
}
__device__ __forceinline__ void cp16(void* sdst, const void* gsrc) {
    uint32_t s = (uint32_t)__cvta_generic_to_shared(sdst);
    asm volatile("cp.async.ca.shared.global [%0], [%1], 16;" :: "r"(s), "l"(gsrc));
}
__device__ __forceinline__ void cp16z(void* sdst, const void* gsrc, bool p) {
    uint32_t s = (uint32_t)__cvta_generic_to_shared(sdst);
    asm volatile("cp.async.ca.shared.global [%0], [%1], 16, %2;" :: "r"(s), "l"(gsrc), "r"(p ? 16 : 0));
}
#define CP_COMMIT() asm volatile("cp.async.commit_group;")
#define CP_WAIT2()  asm volatile("cp.async.wait_group 2;")
#define CP_WAIT1()  asm volatile("cp.async.wait_group 1;")
#define CP_WAIT0()  asm volatile("cp.async.wait_group 0;")

__device__ __forceinline__ float4 silu4(float4 a, float4 b) {
    float4 r;
    r.x = (a.x / (1.f + expf(-a.x))) * b.x;
    r.y = (a.y / (1.f + expf(-a.y))) * b.y;
    r.z = (a.z / (1.f + expf(-a.z))) * b.z;
    r.w = (a.w / (1.f + expf(-a.w))) * b.w;
    return r;
}

// GEMM dynamic smem: As[2][128][72] + Bs[2][64][264] bf16 (K-chunk 64, 2-stage)
constexpr int TG_AS_BYTES = 2 * 128 * 72 * 2;   // 36864
constexpr int TG_SMEM = TG_AS_BYTES + 2 * 64 * 264 * 2;  // 104448

// ============================================================
// fp32 -> bf16 convert (n multiple of 8), 16B stores
// ============================================================
__global__ void f2bf_kernel(const float* __restrict__ in, __nv_bfloat16* __restrict__ out, int n)
{
    int i = (blockIdx.x * TB + threadIdx.x) << 3;
    if (i < n) {
        float4 v0 = *(const float4*)(in + i);
        float4 v1 = *(const float4*)(in + i + 4);
        *(uint4*)(out + i) = f8_to_bf8(v0, v1);
    }
}

// ============================================================
// Strided convert: in [R][1<<shift] fp32 -> out rows of stride ostride
// at column offset ooff. 8 elems/thread, 16B stores.
// ============================================================
__global__ void f2bf_stride(const float* __restrict__ in, __nv_bfloat16* __restrict__ out,
                            int shift, int ostride, int ooff)
{
    int i = (blockIdx.x * TB + threadIdx.x) << 3;
    int r = i >> shift;
    int c = i & ((1 << shift) - 1);
    float4 v0 = *(const float4*)(in + i);
    float4 v1 = *(const float4*)(in + i + 4);
    *(uint4*)(out + (size_t)r * ostride + ooff + c) = f8_to_bf8(v0, v1);
}

// ============================================================
// Paired convert, 128-col interleaved, 8 elems/thread, 16B stores.
// ============================================================
__global__ void f2bf_pair(const float* __restrict__ in1, const float* __restrict__ in2,
                          __nv_bfloat16* __restrict__ out)
{
    size_t zi = (size_t)blockIdx.z * Cv * Iv;
    size_t zo = (size_t)blockIdx.z * Cv * 2 * Iv;
    int i = (blockIdx.x * TB + threadIdx.x) << 3;
    int r = i >> 11;
    int c = i & (Iv - 1);
    int blk = c >> 7, cc = c & 127;
    float4 a0 = *(const float4*)(in1 + zi + i);
    float4 a1 = *(const float4*)(in1 + zi + i + 4);
    float4 b0 = *(const float4*)(in2 + zi + i);
    float4 b1 = *(const float4*)(in2 + zi + i + 4);
    size_t ob = zo + (size_t)r * (2 * Iv) + blk * 256 + cc;
    *(uint4*)(out + ob)       = f8_to_bf8(a0, a1);
    *(uint4*)(out + ob + 128) = f8_to_bf8(b0, b1);
}

// ============================================================
// RMSNorm: one block per token; bf16 output only.
// ============================================================
__global__ void rmsnorm_kernel(const float* __restrict__ x, const float* __restrict__ w,
                               __nv_bfloat16* __restrict__ yb)
{
    int n = blockIdx.x, tid = threadIdx.x;
    const float* xr = x + (size_t)n * Cv;
    __shared__ float red[TB];
    float ss = 0.f;
    for (int c = tid; c < Cv; c += TB) { float v = xr[c]; ss += v * v; }
    red[tid] = ss; __syncthreads();
    for (int s = TB / 2; s > 0; s >>= 1) { if (tid < s) red[tid] += red[tid + s]; __syncthreads(); }
    float rs = rsqrtf(red[0] / (float)Cv + 1e-6f);
    __nv_bfloat16* ybr = yb + (size_t)n * Cv;
    for (int c = tid; c < Cv; c += TB)
        ybr[c] = __float2bfloat16(xr[c] * rs * w[c]);
}

// ============================================================
// RMSNorm + router fused.
// ============================================================
__global__ void rmsnorm_router(const float* __restrict__ x, const float* __restrict__ w,
                               __nv_bfloat16* __restrict__ yb,
                               const float* __restrict__ Wr, const float* __restrict__ rb)
{
    int n = blockIdx.x, tid = threadIdx.x;
    const float* xr = x + (size_t)n * Cv;
    __shared__ float red[TB];
    float ss = 0.f;
    for (int c = tid; c < Cv; c += TB) { float v = xr[c]; ss += v * v; }
    red[tid] = ss; __syncthreads();
    for (int s = TB / 2; s > 0; s >>= 1) { if (tid < s) red[tid] += red[tid + s]; __syncthreads(); }
    float rs = rsqrtf(red[0] / (float)Cv + 1e-6f);
    __nv_bfloat16* ybr = yb + (size_t)n * Cv;
    float part[Ev];
#pragma unroll
    for (int e = 0; e < Ev; e++) part[e] = 0.f;
    for (int c = tid; c < Cv; c += TB) {
        float v = xr[c] * rs * w[c];
        ybr[c] = __float2bfloat16(v);
#pragma unroll
        for (int e = 0; e < Ev; e++) part[e] += v * Wr[c * Ev + e];
    }
    __shared__ float sd[Ev][TB];
#pragma unroll
    for (int e = 0; e < Ev; e++) sd[e][tid] = part[e];
    __syncthreads();
    for (int st = TB / 2; st > 0; st >>= 1) {
        if (tid < st)
#pragma unroll
            for (int e = 0; e < Ev; e++) sd[e][tid] += sd[e][tid + st];
        __syncthreads();
    }
    if (tid == 0) {
        int best = 0; float bp = -1.f;
#pragma unroll
        for (int e = 0; e < Ev; e++) {
            float lg = fminf(fmaxf(sd[e][0] + rb[e], -50.f), 50.f);
            float pr = 1.f / (1.f + expf(-lg));
            if (pr > bp) { bp = pr; best = e; }
        }
        g_sel[n] = best;
        g_p[n]   = fminf(fmaxf(bp, 1e-8f), 1.f - 1e-8f);
    }
}

// ============================================================
// BF16 cp.async 2-stage GEMM, 128x256 block tile, 64x64 warp tile,
// K-chunk 64. C = alpha*A[M,K]@B[K,N(ldB)] (+Res); C rows stride ldC.
// ============================================================
__global__ void __launch_bounds__(256) tgemm_bf(
    const __nv_bfloat16* __restrict__ A, const __nv_bfloat16* __restrict__ B,
    float* __restrict__ Cmat, const float* __restrict__ Res,
    int K, int ldB, int ldC, float alpha)
{
    extern __shared__ char sm[];
    auto As = (__nv_bfloat16 (*)[128][72])sm;
    auto Bs = (__nv_bfloat16 (*)[64][264])(sm + TG_AS_BYTES);
    const int tid  = threadIdx.x;
    const int warp = tid >> 5;
    const int wm   = warp & 1, wn = warp >> 1;
    const int bm   = blockIdx.y * 128, bn = blockIdx.x * 256;

    wmma::fragment<wmma::accumulator, 16, 16, 16, float> acc[4][4];
#pragma unroll
    for (int mi = 0; mi < 4; mi++)
#pragma unroll
        for (int ni = 0; ni < 4; ni++) wmma::fill_fragment(acc[mi][ni], 0.f);

    const int nch = K >> 6;

    auto issue = [&](int stage, int k0) {
#pragma unroll
        for (int i = 0; i < 4; i++) {
            int ch = (i << 8) + tid;
            int ar = ch >> 3, ac = (ch & 7) << 3;
            cp16(&As[stage][ar][ac], A + (size_t)(bm + ar) * K + k0 + ac);
        }
#pragma unroll
        for (int i = 0; i < 8; i++) {
            int ch = (i << 8) + tid;
            int br = ch >> 5, bc = (ch & 31) << 3;
            cp16(&Bs[stage][br][bc], B + (size_t)(k0 + br) * ldB + bn + bc);
        }
    };

    issue(0, 0); CP_COMMIT();

    for (int ch = 0; ch < nch; ch++) {
        CP_WAIT0();
        __syncthreads();
        if (ch + 1 < nch) { issue((ch + 1) & 1, (ch + 1) << 6); CP_COMMIT(); }
        int buf = ch & 1;
#pragma unroll
        for (int ks = 0; ks < 4; ks++) {
            int k16 = ks << 4;
            wmma::fragment<wmma::matrix_a, 16, 16, 16, __nv_bfloat16, wmma::row_major> af[4];
            wmma::fragment<wmma::matrix_b, 16, 16, 16, __nv_bfloat16, wmma::row_major> bf[4];
#pragma unroll
            for (int mi = 0; mi < 4; mi++)
                wmma::load_matrix_sync(af[mi], &As[buf][wm * 64 + mi * 16][k16], 72);
#pragma unroll
            for (int ni = 0; ni < 4; ni++)
                wmma::load_matrix_sync(bf[ni], &Bs[buf][k16][wn * 64 + ni * 16], 264);
#pragma unroll
            for (int mi = 0; mi < 4; mi++)
#pragma unroll
                for (int ni = 0; ni < 4; ni++)
                    wmma::mma_sync(acc[mi][ni], af[mi], bf[ni], acc[mi][ni]);
        }
    }

#pragma unroll
    for (int mi = 0; mi < 4; mi++)
#pragma unroll
        for (int ni = 0; ni < 4; ni++) {
            size_t row = (size_t)(bm + wm * 64 + mi * 16);
            size_t col = (size_t)(bn + wn * 64 + ni * 16);
            float* cp = Cmat + row * ldC + col;
            if (Res) {
                wmma::fragment<wmma::accumulator, 16, 16, 16, float> rf;
                wmma::load_matrix_sync(rf, Res + row * ldC + col, ldC, wmma::mem_row_major);
#pragma unroll
                for (int t = 0; t < rf.num_elements; t++)
                    acc[mi][ni].x[t] = acc[mi][ni].x[t] * alpha + rf.x[t];
            } else if (alpha != 1.f) {
#pragma unroll
                for (int t = 0; t < acc[mi][ni].num_elements; t++)
                    acc[mi][ni].x[t] *= alpha;
            }
            wmma::store_matrix_sync(cp, acc[mi][ni], ldC, wmma::mem_row_major);
        }
}

// ============================================================
// BF16 GEMM + fused SiLU epilogue (dense or grouped/gathered).
// K-chunk 64, 2-stage. B is 128-col interleaved w1|w3 [K][2*Iv].
// ============================================================
template <bool GROUPED>
__global__ void __launch_bounds__(256) tgemm_silu(
    const __nv_bfloat16* __restrict__ A, const __nv_bfloat16* __restrict__ Bbase,
    size_t strideB, int K, __nv_bfloat16* __restrict__ U)
{
    constexpr int N = 2 * Iv;   // 4096
    int cnt = Nv, o = 0, base, bnIdx;
    const __nv_bfloat16* B;
    if (GROUPED) {
        int e = blockIdx.z;
        cnt = g_cnt[e];
        base = blockIdx.x * 128;
        if (base >= cnt) return;
        o = g_off[e];
        bnIdx = blockIdx.y;
        B = Bbase + (size_t)e * strideB;
    } else {
        base = blockIdx.y * 128;
        bnIdx = blockIdx.x;
        B = Bbase;
    }
    const int bn = bnIdx * 256;

    extern __shared__ char sm[];
    auto As = (__nv_bfloat16 (*)[128][72])sm;
    auto Bs = (__nv_bfloat16 (*)[64][264])(sm + TG_AS_BYTES);
    const int tid  = threadIdx.x;
    const int warp = tid >> 5;
    const int wm   = warp & 1, wn = warp >> 1;

    wmma::fragment<wmma::accumulator, 16, 16, 16, float> acc[4][4];
#pragma unroll
    for (int mi = 0; mi < 4; mi++)
#pragma unroll
        for (int ni = 0; ni < 4; ni++) wmma::fill_fragment(acc[mi][ni], 0.f);

    int grow[4]; bool gv[4]; int arr[4]; int arc[4];
#pragma unroll
    for (int i = 0; i < 4; i++) {
        int ch = (i << 8) + tid;
        arr[i] = ch >> 3; arc[i] = (ch & 7) << 3;
        int lr = base + arr[i];
        gv[i] = lr < cnt;
        grow[i] = gv[i] ? (GROUPED ? g_perm[o + lr] : lr) : 0;
    }

    const int nch = K >> 6;

    auto issue = [&](int stg, int k0) {
#pragma unroll
        for (int i = 0; i < 4; i++)
            cp16z(&As[stg][arr[i]][arc[i]], A + (size_t)grow[i] * K + k0 + arc[i], gv[i]);
#pragma unroll
        for (int i = 0; i < 8; i++) {
            int ch = (i << 8) + tid;
            int br = ch >> 5, bc = (ch & 31) << 3;
            cp16(&Bs[stg][br][bc], B + (size_t)(k0 + br) * N + bn + bc);
        }
    };

    issue(0, 0); CP_COMMIT();

    for (int ch = 0; ch < nch; ch++) {
        CP_WAIT0();
        __syncthreads();
        if (ch + 1 < nch) { issue((ch + 1) & 1, (ch + 1) << 6); CP_COMMIT(); }
        int buf = ch & 1;
#pragma unroll
        for (int ks = 0; ks < 4; ks++) {
            int k16 = ks << 4;
            wmma::fragment<wmma::matrix_a, 16, 16, 16, __nv_bfloat16, wmma::row_major> af[4];
            wmma::fragment<wmma::matrix_b, 16, 16, 16, __nv_bfloat16, wmma::row_major> bf[4];
#pragma unroll
            for (int mi = 0; mi < 4; mi++)
                wmma::load_matrix_sync(af[mi], &As[buf][wm * 64 + mi * 16][k16], 72);
#pragma unroll
            for (int ni = 0; ni < 4; ni++)
                wmma::load_matrix_sync(bf[ni], &Bs[buf][k16][wn * 64 + ni * 16], 264);
#pragma unroll
            for (int mi = 0; mi < 4; mi++)
#pragma unroll
                for (int ni = 0; ni < 4; ni++)
                    wmma::mma_sync(acc[mi][ni], af[mi], bf[ni], acc[mi][ni]);
        }
    }

    // fused SiLU epilogue: stage 32x256 fp32 per mi, pair left/right halves.
    __syncthreads();
    float* S = (float*)sm;                  // 32 rows x ldm 264
    const int er = tid >> 3;
    const int ec = (tid & 7) << 4;
#pragma unroll
    for (int mi = 0; mi < 4; mi++) {
#pragma unroll
        for (int ni = 0; ni < 4; ni++)
            wmma::store_matrix_sync(S + (wm * 16) * 264 + wn * 64 + ni * 16,
                                    acc[mi][ni], 264, wmma::mem_row_major);
        __syncthreads();
        int lr = base + (er >> 4) * 64 + mi * 16 + (er & 15);
        if (lr < cnt) {
            size_t row = (size_t)(GROUPED ? (o + lr) : lr);
            __nv_bfloat16* op = U + row * Iv + bnIdx * 128 + ec;
            const float* sp = S + er * 264 + ec;
#pragma unroll
            for (int j = 0; j < 16; j += 4) {
                float4 a = *(const float4*)(sp + j);
                float4 b = *(const float4*)(sp + 128 + j);
                *(uint2*)(op + j) = f4_to_bf4(silu4(a, b));
            }
        }
        __syncthreads();
    }
}

// ============================================================
// Grouped w2 GEMM + fused combine epilogue. K-chunk 64, 2-stage.
// ============================================================
__global__ void __launch_bounds__(256) gg_w2_combine(
    const __nv_bfloat16* __restrict__ A, const __nv_bfloat16* __restrict__ Bbase,
    size_t strideB, int K,
    const float* __restrict__ x1, const float* __restrict__ sh,
    float* __restrict__ Out)
{
    constexpr int N = Cv;
    int e = blockIdx.z;
    int cnt = g_cnt[e];
    int base = blockIdx.x * 128;
    if (base >= cnt) return;
    int o = g_off[e];
    const __nv_bfloat16* B = Bbase + (size_t)e * strideB;

    extern __shared__ char sm[];
    auto As = (__nv_bfloat16 (*)[128][72])sm;
    auto Bs = (__nv_bfloat16 (*)[64][264])(sm + TG_AS_BYTES);
    const int tid  = threadIdx.x;
    const int warp = tid >> 5;
    const int lane = tid & 31;
    const int wm   = warp & 1, wn = warp >> 1;
    const int bn   = blockIdx.y * 256;

    wmma::fragment<wmma::accumulator, 16, 16, 16, float> acc[4][4];
#pragma unroll
    for (int mi = 0; mi < 4; mi++)
#pragma unroll
        for (int ni = 0; ni < 4; ni++) wmma::fill_fragment(acc[mi][ni], 0.f);

    int grow[4]; bool gv[4]; int arr[4]; int arc[4];
#pragma unroll
    for (int i = 0; i < 4; i++) {
        int ch = (i << 8) + tid;
        arr[i] = ch >> 3; arc[i] = (ch & 7) << 3;
        int lr = base + arr[i];
        gv[i] = lr < cnt;
        grow[i] = gv[i] ? (o + lr) : 0;   // compact rows (no gather)
    }

    const int nch = K >> 6;

    auto issue = [&](int stg, int k0) {
#pragma unroll
        for (int i = 0; i < 4; i++)
            cp16z(&As[stg][arr[i]][arc[i]], A + (size_t)grow[i] * K + k0 + arc[i], gv[i]);
#pragma unroll
        for (int i = 0; i < 8; i++) {
            int ch = (i << 8) + tid;
            int br = ch >> 5, bc = (ch & 31) << 3;
            cp16(&Bs[stg][br][bc], B + (size_t)(k0 + br) * N + bn + bc);
        }
    };

    issue(0, 0); CP_COMMIT();

    for (int ch = 0; ch < nch; ch++) {
        CP_WAIT0();
        __syncthreads();
        if (ch + 1 < nch) { issue((ch + 1) & 1, (ch + 1) << 6); CP_COMMIT(); }
        int buf = ch & 1;
#pragma unroll
        for (int ks = 0; ks < 4; ks++) {
            int k16 = ks << 4;
            wmma::fragment<wmma::matrix_a, 16, 16, 16, __nv_bfloat16, wmma::row_major> af[4];
            wmma::fragment<wmma::matrix_b, 16, 16, 16, __nv_bfloat16, wmma::row_major> bf[4];
#pragma unroll
            for (int mi = 0; mi < 4; mi++)
                wmma::load_matrix_sync(af[mi], &As[buf][wm * 64 + mi * 16][k16], 72);
#pragma unroll
            for (int ni = 0; ni < 4; ni++)
                wmma::load_matrix_sync(bf[ni], &Bs[buf][k16][wn * 64 + ni * 16], 264);
#pragma unroll
            for (int mi = 0; mi < 4; mi++)
#pragma unroll
                for (int ni = 0; ni < 4; ni++)
                    wmma::mma_sync(acc[mi][ni], af[mi], bf[ni], acc[mi][ni]);
        }
    }

    __syncthreads();   // done with As/Bs; reuse smem as epilogue stage
    float* stg = (float*)sm + warp * 320;   // 16 rows x ldm 20
    const int sr = lane >> 1, sc0 = (lane & 1) << 3;
#pragma unroll
    for (int mi = 0; mi < 4; mi++)
#pragma unroll
        for (int ni = 0; ni < 4; ni++) {
            wmma::store_matrix_sync(stg, acc[mi][ni], 20, wmma::mem_row_major);
            __syncwarp();
            int lr = base + wm * 64 + mi * 16 + sr;
            if (lr < cnt) {
                int n = g_perm[o + lr];
                float p = g_p[n];
                float tw = fminf(fmaxf(0.5f + p + 1e-8f, 0.5f), 2.0f);
                float wsh = 0.5f / tw, wex = p / tw;
                int col = bn + wn * 64 + ni * 16 + sc0;
                const float* xr = x1 + (size_t)n * Cv + col;
                const float* sr2 = sh + (size_t)n * Cv + col;
                float* orow = Out + (size_t)n * Cv + col;
                float4 a0 = *(float4*)(stg + sr * 20 + sc0);
                float4 a1 = *(float4*)(stg + sr * 20 + sc0 + 4);
                float4 xv0 = *(const float4*)(xr);
                float4 xv1 = *(const float4*)(xr + 4);
                float4 sv0 = *(const float4*)(sr2);
                float4 sv1 = *(const float4*)(sr2 + 4);
                float4 r0, r1;
                r0.x = xv0.x + wsh * sv0.x + wex * a0.x;
                r0.y = xv0.y + wsh * sv0.y + wex * a0.y;
                r0.z = xv0.z + wsh * sv0.z + wex * a0.z;
                r0.w = xv0.w + wsh * sv0.w + wex * a0.w;
                r1.x = xv1.x + wsh * sv1.x + wex * a1.x;
                r1.y = xv1.y + wsh * sv1.y + wex * a1.y;
                r1.z = xv1.z + wsh * sv1.z + wex * a1.z;
                r1.w = xv1.w + wsh * sv1.w + wex * a1.w;
                *(float4*)(orow)     = r0;
                *(float4*)(orow + 4) = r1;
            }
            __syncwarp();
        }
}

// ============================================================
// K/V up-projection, bf16 wmma. grid (Nv/128, Hv*2). (fp32 inputs)
// ============================================================
__global__ void kvup_wmma(const float* __restrict__ kv,
                          const float* __restrict__ Wk_up, const float* __restrict__ Wv_up,
                          float* __restrict__ kout, float* __restrict__ vout)
{
    int y = blockIdx.y;
    int h = y >> 1, which = y & 1;
    const float* W = (which ? Wv_up : Wk_up) + (size_t)h * Lv * Dv;
    float* outp = which ? vout : kout;
    int bm = blockIdx.x * 128;

    __shared__ __nv_bfloat16 As[2][128][40];
    __shared__ __nv_bfloat16 Bs[2][32][72];
    const int tid  = threadIdx.x;
    const int warp = tid >> 5;
    const int wm   = warp & 3, wn = warp >> 2;

    wmma::fragment<wmma::accumulator, 16, 16, 16, float> acc[2][2];
#pragma unroll
    for (int mi = 0; mi < 2; mi++)
#pragma unroll
        for (int ni = 0; ni < 2; ni++) wmma::fill_fragment(acc[mi][ni], 0.f);

    const int ar0 = tid >> 3, ac = (tid & 7) << 2;
    const int br0 = tid >> 4, bc = (tid & 15) << 2;

    float4 aR[4], bR[2];
    const int nch = Lv >> 5;

#pragma unroll
    for (int i = 0; i < 4; i++)
        aR[i] = *(const float4*)(kv + (size_t)(bm + ar0 + (i << 5)) * Lv + ac);
#pragma unroll
    for (int i = 0; i < 2; i++)
        bR[i] = *(const float4*)(W + (size_t)(br0 + (i << 4)) * Dv + bc);
#pragma unroll
    for (int i = 0; i < 4; i++)
        *(uint2*)&As[0][ar0 + (i << 5)][ac] = f4_to_bf4(aR[i]);
#pragma unroll
    for (int i = 0; i < 2; i++)
        *(uint2*)&Bs[0][br0 + (i << 4)][bc] = f4_to_bf4(bR[i]);
    __syncthreads();

    int cur = 0;
    for (int ch = 0; ch < nch; ch++) {
        bool has = (ch + 1) < nch;
        if (has) {
            int k0 = (ch + 1) << 5;
#pragma unroll
            for (int i = 0; i < 4; i++)
                aR[i] = *(const float4*)(kv + (size_t)(bm + ar0 + (i << 5)) * Lv + k0 + ac);
#pragma unroll
            for (int i = 0; i < 2; i++)
                bR[i] = *(const float4*)(W + (size_t)(k0 + br0 + (i << 4)) * Dv + bc);
        }
#pragma unroll
        for (int ks = 0; ks < 2; ks++) {
            int k16 = ks << 4;
            wmma::fragment<wmma::matrix_a, 16, 16, 16, __nv_bfloat16, wmma::row_major> af[2];
            wmma::fragment<wmma::matrix_b, 16, 16, 16, __nv_bfloat16, wmma::row_major> bf[2];
#pragma unroll
            for (int mi = 0; mi < 2; mi++)
                wmma::load_matrix_sync(af[mi], &As[cur][wm * 32 + mi * 16][k16], 40);
#pragma unroll
            for (int ni = 0; ni < 2; ni++)
                wmma::load_matrix_sync(bf[ni], &Bs[cur][k16][wn * 32 + ni * 16], 72);
#pragma unroll
            for (int mi = 0; mi < 2; mi++)
#pragma unroll
                for (int ni = 0; ni < 2; ni++)
                    wmma::mma_sync(acc[mi][ni], af[mi], bf[ni], acc[mi][ni]);
        }
        if (has) {
            int nxt = cur ^ 1;
#pragma unroll
            for (int i = 0; i < 4; i++)
                *(uint2*)&As[nxt][ar0 + (i << 5)][ac] = f4_to_bf4(aR[i]);
#pragma unroll
            for (int i = 0; i < 2; i++)
                *(uint2*)&Bs[nxt][br0 + (i << 4)][bc] = f4_to_bf4(bR[i]);
        }
        __syncthreads();
        cur ^= 1;
    }

#pragma unroll
    for (int mi = 0; mi < 2; mi++) {
        int n0 = bm + wm * 32 + mi * 16;
        int b = n0 >> 10, t0 = n0 & 1023;
        float* bp = outp + ((size_t)(b * Hv + h) * Tv + t0) * Dv;
#pragma unroll
        for (int ni = 0; ni < 2; ni++)
            wmma::store_matrix_sync(bp + wn * 32 + ni * 16, acc[mi][ni], Dv, wmma::mem_row_major);
    }
}

// ============================================================
// RoPE in place on 64-wide head vectors. posDiv: Hv for q-layout, 1 for k.
// ============================================================
__global__ void rope_kernel(float* __restrict__ xp, int posDiv)
{
    int idx = blockIdx.x * TB + threadIdx.x;
    int outer = idx >> 5;
    int j = idx & 31;
    int pos = (outer / posDiv) & (Tv - 1);
    float invf = powf(100000.0f, -(float)j * (1.0f / 32.0f));
    float f = (float)pos * invf;
    float s, c; sincosf(f, &s, &c);
    float* p = xp + (size_t)outer * Dv;
    float x1 = p[j], x2 = p[j + 32];
    p[j]      = x1 * c - x2 * s;
    p[j + 32] = x1 * s + x2 * c;
}

// ============================================================
// Flash attention, 64-row Q tile, K double-buffered + V late-wait
// (tf32 wmma, online softmax). Out bf16 token-major. grid (Tv/64, BHv).
// ============================================================
constexpr int FLASH_SMEM = (6 * 64 * 68 + 3 * 64) * 4;   // ~102.8KB -> 2 blocks/SM

__global__ void __launch_bounds__(256) flash_kernel(
    const float* __restrict__ q, const float* __restrict__ k,
    const float* __restrict__ v, __nv_bfloat16* __restrict__ obf)
{
    extern __shared__ float fs[];
    float (*Qs)[68] = (float(*)[68])fs;
    float (*Os)[68] = (float(*)[68])(fs + 64 * 68);
    float (*Ss)[68] = (float(*)[68])(fs + 2 * 64 * 68);
    float (*Ks)[64][68] = (float(*)[64][68])(fs + 3 * 64 * 68);   // 2 buffers
    float (*Vs)[68] = (float(*)[68])(fs + 5 * 64 * 68);
    float* mrow = fs + 6 * 64 * 68;
    float* lrow = mrow + 64;
    float* srow = lrow + 64;

    const int qt = blockIdx.x, bh = blockIdx.y;
    const int b = bh >> 4, h = bh & 15;
    const int qs = qt * 64;
    const int tid = threadIdx.x;
    const int warp = tid >> 5;
    const int wm = warp & 3, wn = warp >> 2;
    const int row = tid >> 2, qd = tid & 3;

    // load Q tile (group Q)
#pragma unroll
    for (int i = 0; i < 4; i++) {
        int ch = (i << 8) + tid;
        int r = ch >> 4, c = (ch & 15) << 2;
        cp16(&Qs[r][c], q + (size_t)(b * Tv + qs + r) * Cv + h * Dv + c);
    }
    CP_COMMIT();
    for (int i = tid; i < 64 * 68; i += 256) (fs + 64 * 68)[i] = 0.f;
    if (tid < 64) { mrow[tid] = -1e30f; lrow[tid] = 0.f; }

    auto issueK = [&](int buf, int kt) {
        int ks = kt * 64;
#pragma unroll
        for (int i = 0; i < 4; i++) {
            int ch = (i << 8) + tid;
            int r = ch >> 4, c = (ch & 15) << 2;
            cp16(&Ks[buf][r][c], k + ((size_t)bh * Tv + ks + r) * Dv + c);
        }
    };
    issueK(0, 0); CP_COMMIT();   // pending: Q, K0

    for (int kt = 0; kt <= qt; kt++) {
        int ks = kt * 64;
        // issue V[kt]
#pragma unroll
        for (int i = 0; i < 4; i++) {
            int ch = (i << 8) + tid;
            int r = ch >> 4, c = (ch & 15) << 2;
            cp16(&Vs[r][c], v + ((size_t)bh * Tv + ks + r) * Dv + c);
        }
        CP_COMMIT();
        bool has = kt < qt;
        if (has) { issueK((kt + 1) & 1, kt + 1); CP_COMMIT(); CP_WAIT2(); }
        else     { CP_WAIT1(); }
        __syncthreads();
        const int buf = kt & 1;

        // S = Q K^T / 8 -> Ss
        {
            wmma::fragment<wmma::accumulator, 16, 16, 8, float> a0, a1;
            wmma::fill_fragment(a0, 0.f); wmma::fill_fragment(a1, 0.f);
#pragma unroll
            for (int k8 = 0; k8 < 64; k8 += 8) {
                wmma::fragment<wmma::matrix_a, 16, 16, 8, wmma::precision::tf32, wmma::row_major> af;
                wmma::fragment<wmma::matrix_b, 16, 16, 8, wmma::precision::tf32, wmma::col_major> bf0, bf1;
                wmma::load_matrix_sync(af, &Qs[wm * 16][k8], 68);
                wmma::load_matrix_sync(bf0, &Ks[buf][wn * 32][k8], 68);
                wmma::load_matrix_sync(bf1, &Ks[buf][wn * 32 + 16][k8], 68);
                wmma::mma_sync(a0, af, bf0, a0);
                wmma::mma_sync(a1, af, bf1, a1);
            }
#pragma unroll
            for (int t = 0; t < a0.num_elements; t++) { a0.x[t] *= 0.125f; a1.x[t] *= 0.125f; }
            wmma::store_matrix_sync(&Ss[wm * 16][wn * 32], a0, 68, wmma::mem_row_major);
            wmma::store_matrix_sync(&Ss[wm * 16][wn * 32 + 16], a1, 68, wmma::mem_row_major);
        }
        __syncthreads();

        // online softmax row update
        {
            const bool diag = (kt == qt);
            float sv[16];
            float mloc = -1e30f;
#pragma unroll
            for (int i = 0; i < 16; i++) {
                int j = qd + (i << 2);
                float s = Ss[row][j];
                if (diag && j > row) s = -1e30f;
                sv[i] = s;
                mloc = fmaxf(mloc, s);
            }
            mloc = fmaxf(mloc, __shfl_xor_sync(0xffffffffu, mloc, 1));
            mloc = fmaxf(mloc, __shfl_xor_sync(0xffffffffu, mloc, 2));
            float mold = mrow[row];
            float mnew = fmaxf(mold, mloc);
            float psum = 0.f;
#pragma unroll
            for (int i = 0; i < 16; i++) {
                int j = qd + (i << 2);
                float p = (sv[i] > -1e29f) ? expf(sv[i] - mnew) : 0.f;
                Ss[row][j] = to_tf32(p);
                psum += p;
            }
            psum += __shfl_xor_sync(0xffffffffu, psum, 1);
            psum += __shfl_xor_sync(0xffffffffu, psum, 2);
            if (qd == 0) {
                float scl = expf(mold - mnew);
                mrow[row] = mnew;
                lrow[row] = lrow[row] * scl + psum;
                srow[row] = scl;
            }
        }
        // wait for V[kt] (hidden behind QK + softmax)
        if (has) CP_WAIT1(); else CP_WAIT0();
        __syncthreads();

        // PV -> Ss (reuse; P fragments preloaded before overwrite)
        {
            wmma::fragment<wmma::matrix_a, 16, 16, 8, wmma::precision::tf32, wmma::row_major> af[8];
#pragma unroll
            for (int kk = 0; kk < 8; kk++)
                wmma::load_matrix_sync(af[kk], &Ss[wm * 16][kk * 8], 68);
            __syncthreads();
            wmma::fragment<wmma::accumulator, 16, 16, 8, float> a0, a1;
            wmma::fill_fragment(a0, 0.f); wmma::fill_fragment(a1, 0.f);
#pragma unroll
            for (int kk = 0; kk < 8; kk++) {
                wmma::fragment<wmma::matrix_b, 16, 16, 8, wmma::precision::tf32, wmma::row_major> bf0, bf1;
                wmma::load_matrix_sync(bf0, &Vs[kk * 8][wn * 32], 68);
                wmma::load_matrix_sync(bf1, &Vs[kk * 8][wn * 32 + 16], 68);
                wmma::mma_sync(a0, af[kk], bf0, a0);
                wmma::mma_sync(a1, af[kk], bf1, a1);
            }
            wmma::store_matrix_sync(&Ss[wm * 16][wn * 32], a0, 68, wmma::mem_row_major);
            wmma::store_matrix_sync(&Ss[wm * 16][wn * 32 + 16], a1, 68, wmma::mem_row_major);
        }
        __syncthreads();

        // O = O*scale + PV
        {
            float scl = srow[row];
#pragma unroll
            for (int i = 0; i < 16; i++) {
                int j = qd + (i << 2);
                Os[row][j] = Os[row][j] * scl + Ss[row][j];
            }
        }
        __syncthreads();
    }

    // epilogue: normalize, write bf16 token-major
    {
        float inv = 1.f / lrow[row];
        __nv_bfloat16* op = obf + (size_t)(b * Tv + qs + row) * Cv + h * Dv;
#pragma unroll
        for (int i = 0; i < 16; i++) {
            int j = qd + (i << 2);
            op[j] = __float2bfloat16(Os[row][j] * inv);
        }
    }
}

__global__ void zero_kernel() {
    int t = threadIdx.x;
    if (t < Ev) { g_cnt[t] = 0; g_cur[t] = 0; }
}
__global__ void hist_kernel() {
    int n = blockIdx.x * TB + threadIdx.x;
    if (n < Nv) atomicAdd(&g_cnt[g_sel[n]], 1);
}
__global__ void offsets_kernel() {
    int s = 0;
    for (int e = 0; e < Ev; e++) { g_off[e] = s; s += g_cnt[e]; }
}
__global__ void scatter_kernel() {
    int n = blockIdx.x * TB + threadIdx.x;
    if (n < Nv) {
        int e = g_sel[n];
        int pos = atomicAdd(&g_cur[e], 1);
        g_perm[g_off[e] + pos] = n;
    }
}

// ============================================================
// Static streams/events (created at program init; no device alloc).
// ============================================================
struct StreamPack {
    cudaStream_t sConv, sAux;
    cudaEvent_t evRoot, evQkv, evWo, evMoe, evAux, evH2, evSh, evNorm, evQ;
    StreamPack() {
        cudaStreamCreateWithFlags(&sConv, cudaStreamNonBlocking);
        cudaStreamCreateWithFlags(&sAux,  cudaStreamNonBlocking);
        cudaEventCreateWithFlags(&evRoot,  cudaEventDisableTiming);
        cudaEventCreateWithFlags(&evQkv,   cudaEventDisableTiming);
        cudaEventCreateWithFlags(&evWo,    cudaEventDisableTiming);
        cudaEventCreateWithFlags(&evMoe,   cudaEventDisableTiming);
        cudaEventCreateWithFlags(&evAux,   cudaEventDisableTiming);
        cudaEventCreateWithFlags(&evH2,    cudaEventDisableTiming);
        cudaEventCreateWithFlags(&evSh,    cudaEventDisableTiming);
        cudaEventCreateWithFlags(&evNorm,  cudaEventDisableTiming);
        cudaEventCreateWithFlags(&evQ,     cudaEventDisableTiming);
    }
};
static StreamPack g_sp;

// ============================================================
// launcher
// ============================================================
extern "C" void kernel_launch(void* const* d_in, const int* in_sizes, int n_in,
                              void* d_out, int out_size)
{
    const float* x    = (const float*)d_in[0];
    const float* ln1  = (const float*)d_in[1];
    const float* ln2  = (const float*)d_in[2];
    const float* Wq   = (const float*)d_in[3];
    const float* Wkv  = (const float*)d_in[4];
    const float* Wk_up= (const float*)d_in[5];
    const float* Wv_up= (const float*)d_in[6];
    const float* Wo   = (const float*)d_in[7];
    const float* Wr   = (const float*)d_in[8];
    const float* rb   = (const float*)d_in[9];
    const float* sw1  = (const float*)d_in[10];
    const float* sw2  = (const float*)d_in[11];
    const float* sw3  = (const float*)d_in[12];
    const float* ew1  = (const float*)d_in[13];
    const float* ew2  = (const float*)d_in[14];
    const float* ew3  = (const float*)d_in[15];
    float* out = (float*)d_out;

    float *pkv, *pq, *pk, *pv, *px1, *psh;
    __nv_bfloat16 *phbf, *ph2bf, *patbf, *pubf, *pucbf;
    __nv_bfloat16 *wqkv, *wo, *s13, *s2, *e13, *e2;
    cudaGetSymbolAddress((void**)&pkv, g_kv);
    cudaGetSymbolAddress((void**)&pq,  g_q);
    cudaGetSymbolAddress((void**)&pk,  g_k);
    cudaGetSymbolAddress((void**)&pv,  g_v);
    cudaGetSymbolAddress((void**)&px1, g_x1);
    cudaGetSymbolAddress((void**)&psh, g_sh);
    cudaGetSymbolAddress((void**)&phbf,  g_hbf);
    cudaGetSymbolAddress((void**)&ph2bf, g_h2bf);
    cudaGetSymbolAddress((void**)&patbf, g_atbf);
    cudaGetSymbolAddress((void**)&pubf,  g_ubf);
    cudaGetSymbolAddress((void**)&pucbf, g_ucbf);
    cudaGetSymbolAddress((void**)&wqkv, g_wqkv_bf);
    cudaGetSymbolAddress((void**)&wo,  g_Wo_bf);
    cudaGetSymbolAddress((void**)&s13, g_s13_bf);
    cudaGetSymbolAddress((void**)&s2,  g_sw2_bf);
    cudaGetSymbolAddress((void**)&e13, g_e13_bf);
    cudaGetSymbolAddress((void**)&e2,  g_ew2_bf);

    cudaFuncSetAttribute(flash_kernel, cudaFuncAttributeMaxDynamicSharedMemorySize, FLASH_SMEM);
    cudaFuncSetAttribute(tgemm_bf, cudaFuncAttributeMaxDynamicSharedMemorySize, TG_SMEM);
    cudaFuncSetAttribute(tgemm_silu<false>, cudaFuncAttributeMaxDynamicSharedMemorySize, TG_SMEM);
    cudaFuncSetAttribute(tgemm_silu<true>,  cudaFuncAttributeMaxDynamicSharedMemorySize, TG_SMEM);
    cudaFuncSetAttribute(gg_w2_combine, cudaFuncAttributeMaxDynamicSharedMemorySize, TG_SMEM);

    cudaStream_t sConv = g_sp.sConv, sAux = g_sp.sAux;

    // ---- fork: weight conversion on side stream ----
    cudaEventRecord(g_sp.evRoot, 0);
    cudaStreamWaitEvent(sConv, g_sp.evRoot, 0);
    f2bf_stride<<<(Cv * Cv) / (TB * 8), TB, 0, sConv>>>(Wq,  wqkv, 10, QKVN, 0);
    f2bf_stride<<<(Cv * Lv) / (TB * 8), TB, 0, sConv>>>(Wkv, wqkv, 8,  QKVN, Cv);
    cudaEventRecord(g_sp.evQkv, sConv);
    f2bf_kernel<<<(Cv * Cv) / (TB * 8), TB, 0, sConv>>>(Wo, wo, Cv * Cv);
    cudaEventRecord(g_sp.evWo, sConv);
    f2bf_pair<<<dim3((Cv * Iv) / (TB * 8), 1, 1),  TB, 0, sConv>>>(sw1, sw3, s13);
    f2bf_kernel<<<(Iv * Cv) / (TB * 8), TB, 0, sConv>>>(sw2, s2, Iv * Cv);
    f2bf_pair<<<dim3((Cv * Iv) / (TB * 8), 1, Ev), TB, 0, sConv>>>(ew1, ew3, e13);
    f2bf_kernel<<<(Ev * Iv * Cv) / (TB * 8), TB, 0, sConv>>>(ew2, e2, Ev * Iv * Cv);
    cudaEventRecord(g_sp.evMoe, sConv);

    // ---- attention ----
    rmsnorm_kernel<<<Nv, TB>>>(x, ln1, phbf);
    cudaEventRecord(g_sp.evNorm, 0);

    // q-slice GEMM + rope_q on sAux (concurrent with kv chain)
    cudaStreamWaitEvent(sAux, g_sp.evNorm, 0);
    cudaStreamWaitEvent(sAux, g_sp.evQkv, 0);
    tgemm_bf<<<dim3(Cv / 256, Nv / 128), TB, TG_SMEM, sAux>>>(phbf, wqkv, pq, nullptr, Cv, QKVN, Cv, 1.f);
    rope_kernel<<<(Nv * Hv * 32) / TB, TB, 0, sAux>>>(pq, Hv);
    cudaEventRecord(g_sp.evQ, sAux);

    // kv-slice GEMM + kvup + rope_k on main
    cudaStreamWaitEvent(0, g_sp.evQkv, 0);
    tgemm_bf<<<dim3(Lv / 256, Nv / 128), TB, TG_SMEM>>>(phbf, wqkv + Cv, pkv, nullptr, Cv, QKVN, Lv, 0.25f);
    kvup_wmma<<<dim3(Nv / 128, Hv * 2), TB>>>(pkv, Wk_up, Wv_up, pk, pv);
    rope_kernel<<<(Nv * Hv * 32) / TB, TB>>>(pk, 1);

    cudaStreamWaitEvent(0, g_sp.evQ, 0);
    flash_kernel<<<dim3(Tv / 64, BHv), TB, FLASH_SMEM>>>(pq, pk, pv, patbf);
    cudaStreamWaitEvent(0, g_sp.evWo, 0);
    tgemm_bf<<<dim3(Cv / 256, Nv / 128), TB, TG_SMEM>>>(patbf, wo, px1, x, Cv, Cv, Cv, 1.f);

    // ---- MoE ----
    rmsnorm_router<<<Nv, TB>>>(px1, ln2, ph2bf, Wr, rb);
    cudaEventRecord(g_sp.evH2, 0);

    // routing bookkeeping on aux stream
    cudaStreamWaitEvent(sAux, g_sp.evH2, 0);
    zero_kernel<<<1, 32, 0, sAux>>>();
    hist_kernel<<<Nv / TB, TB, 0, sAux>>>();
    offsets_kernel<<<1, 1, 0, sAux>>>();
    scatter_kernel<<<Nv / TB, TB, 0, sAux>>>();
    cudaEventRecord(g_sp.evAux, sAux);

    // shared-expert chain on sConv (s13/s2 converts are in-order earlier on sConv)
    cudaStreamWaitEvent(sConv, g_sp.evH2, 0);
    tgemm_silu<false><<<dim3((2 * Iv) / 256, Nv / 128), TB, TG_SMEM, sConv>>>(ph2bf, s13, 0, Cv, pubf);
    tgemm_bf<<<dim3(Cv / 256, Nv / 128), TB, TG_SMEM, sConv>>>(pubf, s2, psh, nullptr, Iv, Cv, Cv, 1.f);
    cudaEventRecord(g_sp.evSh, sConv);

    // routed-expert chain on main stream (concurrent with shared chain)
    cudaStreamWaitEvent(0, g_sp.evMoe, 0);
    cudaStreamWaitEvent(0, g_sp.evAux, 0);
    tgemm_silu<true><<<dim3(Nv / 128, (2 * Iv) / 256, Ev), TB, TG_SMEM>>>(ph2bf, e13, (size_t)Cv * 2 * Iv, Cv, pucbf);
    cudaStreamWaitEvent(0, g_sp.evSh, 0);
    gg_w2_combine<<<dim3(Nv / 128, Cv / 256, Ev), TB, TG_SMEM>>>(pucbf, e2, (size_t)Iv * Cv, Iv, px1, psh, out);
}